// round 1
// baseline (speedup 1.0000x reference)
#include <cuda_runtime.h>

// Problem constants
#define Bq   2
#define Nq   8192
#define Cq   512
#define Hq   8
#define Dq   64
#define BHq  16          // B*H
#define Lq   64          // chunk length
#define NCq  128         // chunks per (b,h)  = Nq/Lq
#define Mq   16384       // B*N rows

// Scratch (static device allocations — no cudaMalloc allowed)
__device__ float g_q[(size_t)BHq * Nq * Dq];   // [bh, n, d]
__device__ float g_k[(size_t)BHq * Nq * Dq];
__device__ float g_v[(size_t)BHq * Nq * Dq];
__device__ float g_s[(size_t)BHq * NCq * Dq * Dq]; // per-chunk K^T V, turned into exclusive prefix in-place
__device__ float g_o[(size_t)Mq * Cq];         // attention output, [b*N+n, h*64+d]

// ---------------------------------------------------------------------------
// GEMM 1: qkv = x @ W_qkv^T, fused elu+1 on q,k parts, scatter to g_q/g_k/g_v
// C[m, j] = sum_k X[m,k] * W[j,k];  M=16384, N=1536, K=512
// ---------------------------------------------------------------------------
__global__ __launch_bounds__(256, 2) void k_gemm_qkv(const float* __restrict__ X,
                                                     const float* __restrict__ W) {
    __shared__ float As[16][132];
    __shared__ float Bs[16][132];
    const int m0 = blockIdx.y * 128;
    const int j0 = blockIdx.x * 128;
    const int tid = threadIdx.x;
    const int tx = tid & 15;
    const int ty = tid >> 4;
    const int lrow = tid >> 2;         // 0..63
    const int lk = (tid & 3) * 4;      // 0,4,8,12

    float acc[8][8];
#pragma unroll
    for (int i = 0; i < 8; i++)
#pragma unroll
        for (int j = 0; j < 8; j++) acc[i][j] = 0.f;

    for (int k0 = 0; k0 < 512; k0 += 16) {
#pragma unroll
        for (int r = 0; r < 2; r++) {
            int row = lrow + r * 64;
            float4 va = *(const float4*)(X + (size_t)(m0 + row) * 512 + k0 + lk);
            As[lk + 0][row] = va.x; As[lk + 1][row] = va.y;
            As[lk + 2][row] = va.z; As[lk + 3][row] = va.w;
            float4 vb = *(const float4*)(W + (size_t)(j0 + row) * 512 + k0 + lk);
            Bs[lk + 0][row] = vb.x; Bs[lk + 1][row] = vb.y;
            Bs[lk + 2][row] = vb.z; Bs[lk + 3][row] = vb.w;
        }
        __syncthreads();
#pragma unroll
        for (int kk = 0; kk < 16; kk++) {
            float a[8], b[8];
            *(float4*)&a[0] = *(const float4*)&As[kk][ty * 8];
            *(float4*)&a[4] = *(const float4*)&As[kk][ty * 8 + 4];
            *(float4*)&b[0] = *(const float4*)&Bs[kk][tx * 8];
            *(float4*)&b[4] = *(const float4*)&Bs[kk][tx * 8 + 4];
#pragma unroll
            for (int i = 0; i < 8; i++)
#pragma unroll
                for (int j = 0; j < 8; j++)
                    acc[i][j] = fmaf(a[i], b[j], acc[i][j]);
        }
        __syncthreads();
    }

#pragma unroll
    for (int i = 0; i < 8; i++) {
        int m = m0 + ty * 8 + i;
        int bb = m >> 13;         // batch
        int n = m & 8191;         // token
#pragma unroll
        for (int j = 0; j < 8; j++) {
            int col = j0 + tx * 8 + j;       // 0..1535
            int p = col >> 9;                // 0=q, 1=k, 2=v
            int h = (col >> 6) & 7;
            int d = col & 63;
            float v = acc[i][j];
            if (p < 2) v = (v > 0.f) ? (v + 1.f) : expf(v);   // elu(x)+1
            float* dst = (p == 0) ? g_q : (p == 1) ? g_k : g_v;
            dst[((size_t)(bb * 8 + h) * 8192 + n) * 64 + d] = v;
        }
    }
}

// ---------------------------------------------------------------------------
// Per-chunk S = K_chunk^T V_chunk   (64x64 per (bh, chunk))
// ---------------------------------------------------------------------------
__global__ __launch_bounds__(256) void k_chunk_kv() {
    __shared__ float Ks[64][68];
    __shared__ float Vs[64][68];
    const int bh = blockIdx.y;
    const int c = blockIdx.x;
    const int tid = threadIdx.x;
    const size_t base = ((size_t)bh * 8192 + c * 64) * 64;

#pragma unroll
    for (int r = 0; r < 4; r++) {
        int f = tid + 256 * r;          // 0..1023
        int row = f >> 4;
        int c4 = (f & 15) * 4;
        *(float4*)&Ks[row][c4] = *(const float4*)(g_k + base + (size_t)row * 64 + c4);
        *(float4*)&Vs[row][c4] = *(const float4*)(g_v + base + (size_t)row * 64 + c4);
    }
    __syncthreads();

    const int d0 = (tid & 15) * 4;
    const int e0 = (tid >> 4) * 4;
    float acc[4][4];
#pragma unroll
    for (int i = 0; i < 4; i++)
#pragma unroll
        for (int j = 0; j < 4; j++) acc[i][j] = 0.f;

#pragma unroll 8
    for (int t = 0; t < 64; t++) {
        float4 k4 = *(const float4*)&Ks[t][d0];
        float4 v4 = *(const float4*)&Vs[t][e0];
        float ka[4] = {k4.x, k4.y, k4.z, k4.w};
        float va[4] = {v4.x, v4.y, v4.z, v4.w};
#pragma unroll
        for (int i = 0; i < 4; i++)
#pragma unroll
            for (int j = 0; j < 4; j++)
                acc[i][j] = fmaf(ka[i], va[j], acc[i][j]);
    }

    float* Sp = g_s + ((size_t)bh * NCq + c) * 4096;
#pragma unroll
    for (int i = 0; i < 4; i++) {
        float4 st = make_float4(acc[i][0], acc[i][1], acc[i][2], acc[i][3]);
        *(float4*)&Sp[(size_t)(d0 + i) * 64 + e0] = st;
    }
}

// ---------------------------------------------------------------------------
// In-place exclusive prefix sum over chunk axis. One thread per (bh, d, e).
// grid = 256 blocks of 256 threads: blockIdx>>4 = bh, low bits = entry group.
// ---------------------------------------------------------------------------
__global__ __launch_bounds__(256) void k_prefix() {
    const int bh = blockIdx.x >> 4;
    const int entry = ((blockIdx.x & 15) << 8) + threadIdx.x;   // 0..4095
    float run = 0.f;
    size_t idx = (size_t)bh * NCq * 4096 + entry;
#pragma unroll 4
    for (int c = 0; c < NCq; c++) {
        float s = g_s[idx];
        g_s[idx] = run;
        run += s;
        idx += 4096;
    }
}

// ---------------------------------------------------------------------------
// Per-chunk attention: out = Q @ P + tril_inclusive(Q K^T) @ V
// 256 threads: t = tid>>2 (token in chunk), qd = tid&3 (16-wide slice of D)
// Dynamic smem: Qs, Ks, Vs, Ps, each [64][68] floats.
// ---------------------------------------------------------------------------
__global__ __launch_bounds__(256) void k_attn() {
    extern __shared__ float sm[];
    float (*Qs)[68] = (float(*)[68])(sm);
    float (*Ks)[68] = (float(*)[68])(sm + 64 * 68);
    float (*Vs)[68] = (float(*)[68])(sm + 2 * 64 * 68);
    float (*Ps)[68] = (float(*)[68])(sm + 3 * 64 * 68);

    const int bh = blockIdx.y;
    const int c = blockIdx.x;
    const int tid = threadIdx.x;
    const int t = tid >> 2;           // 0..63
    const int qd = tid & 3;           // 0..3
    const int e0 = qd * 16;
    const size_t base = ((size_t)bh * 8192 + c * 64) * 64;
    const float* Pg = g_s + ((size_t)bh * NCq + c) * 4096;

#pragma unroll
    for (int r = 0; r < 4; r++) {
        int f = tid + 256 * r;
        int row = f >> 4;
        int c4 = (f & 15) * 4;
        *(float4*)&Qs[row][c4] = *(const float4*)(g_q + base + (size_t)row * 64 + c4);
        *(float4*)&Ks[row][c4] = *(const float4*)(g_k + base + (size_t)row * 64 + c4);
        *(float4*)&Vs[row][c4] = *(const float4*)(g_v + base + (size_t)row * 64 + c4);
        *(float4*)&Ps[row][c4] = *(const float4*)(Pg + (size_t)row * 64 + c4);
    }
    __syncthreads();

    float acc[16];
#pragma unroll
    for (int i = 0; i < 16; i++) acc[i] = 0.f;

    // Phase 1: acc += q_t @ P   (inter-chunk contribution)
#pragma unroll 4
    for (int d = 0; d < 64; d++) {
        float qv = Qs[t][d];
#pragma unroll
        for (int i = 0; i < 16; i += 4) {
            float4 p4 = *(const float4*)&Ps[d][e0 + i];
            acc[i + 0] = fmaf(qv, p4.x, acc[i + 0]);
            acc[i + 1] = fmaf(qv, p4.y, acc[i + 1]);
            acc[i + 2] = fmaf(qv, p4.z, acc[i + 2]);
            acc[i + 3] = fmaf(qv, p4.w, acc[i + 3]);
        }
    }

    // Phase 2: intra-chunk causal part. Partial dot over own 16-wide d slice,
    // butterfly-reduce across the 4 partner lanes, masked accumulate.
    float qp[16];
#pragma unroll
    for (int i = 0; i < 16; i++) qp[i] = Qs[t][e0 + i];

    for (int s = 0; s < 64; s++) {
        float w = 0.f;
#pragma unroll
        for (int i = 0; i < 16; i += 4) {
            float4 k4 = *(const float4*)&Ks[s][e0 + i];
            w = fmaf(qp[i + 0], k4.x, w);
            w = fmaf(qp[i + 1], k4.y, w);
            w = fmaf(qp[i + 2], k4.z, w);
            w = fmaf(qp[i + 3], k4.w, w);
        }
        w += __shfl_xor_sync(0xffffffffu, w, 1);
        w += __shfl_xor_sync(0xffffffffu, w, 2);
        if (s > t) w = 0.f;              // inclusive causal mask (kv updated before out)
#pragma unroll
        for (int i = 0; i < 16; i += 4) {
            float4 v4 = *(const float4*)&Vs[s][e0 + i];
            acc[i + 0] = fmaf(w, v4.x, acc[i + 0]);
            acc[i + 1] = fmaf(w, v4.y, acc[i + 1]);
            acc[i + 2] = fmaf(w, v4.z, acc[i + 2]);
            acc[i + 3] = fmaf(w, v4.w, acc[i + 3]);
        }
    }

    // Store to [b*N+n, h*64+e] layout for the projection GEMM
    const int bb = bh >> 3;
    const int h = bh & 7;
    const int n = c * 64 + t;
    float* op = g_o + ((size_t)bb * 8192 + n) * 512 + h * 64 + e0;
#pragma unroll
    for (int i = 0; i < 16; i += 4)
        *(float4*)(op + i) = make_float4(acc[i], acc[i + 1], acc[i + 2], acc[i + 3]);
}

// ---------------------------------------------------------------------------
// GEMM 2: out = g_o @ W_proj^T + b_proj.   M=16384, N=512, K=512
// ---------------------------------------------------------------------------
__global__ __launch_bounds__(256, 2) void k_gemm_proj(const float* __restrict__ W,
                                                      const float* __restrict__ bias,
                                                      float* __restrict__ out) {
    __shared__ float As[16][132];
    __shared__ float Bs[16][132];
    const int m0 = blockIdx.y * 128;
    const int j0 = blockIdx.x * 128;
    const int tid = threadIdx.x;
    const int tx = tid & 15;
    const int ty = tid >> 4;
    const int lrow = tid >> 2;
    const int lk = (tid & 3) * 4;

    float acc[8][8];
#pragma unroll
    for (int i = 0; i < 8; i++)
#pragma unroll
        for (int j = 0; j < 8; j++) acc[i][j] = 0.f;

    for (int k0 = 0; k0 < 512; k0 += 16) {
#pragma unroll
        for (int r = 0; r < 2; r++) {
            int row = lrow + r * 64;
            float4 va = *(const float4*)(g_o + (size_t)(m0 + row) * 512 + k0 + lk);
            As[lk + 0][row] = va.x; As[lk + 1][row] = va.y;
            As[lk + 2][row] = va.z; As[lk + 3][row] = va.w;
            float4 vb = *(const float4*)(W + (size_t)(j0 + row) * 512 + k0 + lk);
            Bs[lk + 0][row] = vb.x; Bs[lk + 1][row] = vb.y;
            Bs[lk + 2][row] = vb.z; Bs[lk + 3][row] = vb.w;
        }
        __syncthreads();
#pragma unroll
        for (int kk = 0; kk < 16; kk++) {
            float a[8], b[8];
            *(float4*)&a[0] = *(const float4*)&As[kk][ty * 8];
            *(float4*)&a[4] = *(const float4*)&As[kk][ty * 8 + 4];
            *(float4*)&b[0] = *(const float4*)&Bs[kk][tx * 8];
            *(float4*)&b[4] = *(const float4*)&Bs[kk][tx * 8 + 4];
#pragma unroll
            for (int i = 0; i < 8; i++)
#pragma unroll
                for (int j = 0; j < 8; j++)
                    acc[i][j] = fmaf(a[i], b[j], acc[i][j]);
        }
        __syncthreads();
    }

#pragma unroll
    for (int i = 0; i < 8; i++) {
        int m = m0 + ty * 8 + i;
#pragma unroll
        for (int j = 0; j < 8; j += 4) {
            int col = j0 + tx * 8 + j;
            float4 st;
            st.x = acc[i][j + 0] + bias[col + 0];
            st.y = acc[i][j + 1] + bias[col + 1];
            st.z = acc[i][j + 2] + bias[col + 2];
            st.w = acc[i][j + 3] + bias[col + 3];
            *(float4*)(out + (size_t)m * 512 + col) = st;
        }
    }
}

// ---------------------------------------------------------------------------
extern "C" void kernel_launch(void* const* d_in, const int* in_sizes, int n_in,
                              void* d_out, int out_size) {
    const float* x     = (const float*)d_in[0];   // [2, 8192, 512]
    const float* Wqkv  = (const float*)d_in[1];   // [1536, 512]
    const float* Wproj = (const float*)d_in[2];   // [512, 512]
    const float* bproj = (const float*)d_in[3];   // [512]
    float* out = (float*)d_out;                   // [2, 8192, 512]

    (void)in_sizes; (void)n_in; (void)out_size;

    dim3 g1(1536 / 128, 16384 / 128);   // (12, 128)
    k_gemm_qkv<<<g1, 256>>>(x, Wqkv);

    dim3 ga(NCq, BHq);                  // (128, 16)
    k_chunk_kv<<<ga, 256>>>();

    k_prefix<<<256, 256>>>();

    static const int attn_smem = 4 * 64 * 68 * (int)sizeof(float);   // 69632 B
    cudaFuncSetAttribute(k_attn, cudaFuncAttributeMaxDynamicSharedMemorySize, attn_smem);
    k_attn<<<ga, 256, attn_smem>>>();

    dim3 g2(512 / 128, 16384 / 128);    // (4, 128)
    k_gemm_proj<<<g2, 256>>>(Wproj, bproj, out);
}

// round 3
// speedup vs baseline: 1.7024x; 1.7024x over previous
#include <cuda_runtime.h>
#include <cuda_bf16.h>
#include <cstdint>

// Problem constants
#define Bq   2
#define Nq   8192
#define Cq   512
#define Hq   8
#define Dq   64
#define BHq  16
#define Lq   64
#define NCq  128
#define Mq   16384

// ---------------------------------------------------------------------------
// Static device scratch
// ---------------------------------------------------------------------------
__device__ float g_q[(size_t)BHq * Nq * Dq];
__device__ float g_k[(size_t)BHq * Nq * Dq];
__device__ float g_v[(size_t)BHq * Nq * Dq];
__device__ float g_s[(size_t)BHq * NCq * Dq * Dq];

__device__ __align__(16) __nv_bfloat16 g_xhi[(size_t)Mq * Cq];
__device__ __align__(16) __nv_bfloat16 g_xlo[(size_t)Mq * Cq];
__device__ __align__(16) __nv_bfloat16 g_wqh[1536 * 512];
__device__ __align__(16) __nv_bfloat16 g_wql[1536 * 512];
__device__ __align__(16) __nv_bfloat16 g_wph[512 * 512];
__device__ __align__(16) __nv_bfloat16 g_wpl[512 * 512];
__device__ __align__(16) __nv_bfloat16 g_ohi[(size_t)Mq * Cq];
__device__ __align__(16) __nv_bfloat16 g_olo[(size_t)Mq * Cq];

#define SWZ(o) ((o) ^ (((o) >> 3) & 0x70))

__device__ __forceinline__ uint32_t smem_u32(const void* p) {
    uint32_t a;
    asm("{ .reg .u64 t; cvta.to.shared.u64 t, %1; cvt.u32.u64 %0, t; }" : "=r"(a) : "l"(p));
    return a;
}

__device__ __forceinline__ void ldsm_x4(uint32_t* r, uint32_t addr) {
    asm volatile("ldmatrix.sync.aligned.m8n8.x4.shared.b16 {%0,%1,%2,%3}, [%4];"
                 : "=r"(r[0]), "=r"(r[1]), "=r"(r[2]), "=r"(r[3]) : "r"(addr));
}
__device__ __forceinline__ void ldsm_x2(uint32_t* r, uint32_t addr) {
    asm volatile("ldmatrix.sync.aligned.m8n8.x2.shared.b16 {%0,%1}, [%2];"
                 : "=r"(r[0]), "=r"(r[1]) : "r"(addr));
}
__device__ __forceinline__ void mma16816(float* c, const uint32_t* a, const uint32_t* b) {
    asm volatile("mma.sync.aligned.m16n8k16.row.col.f32.bf16.bf16.f32 "
                 "{%0,%1,%2,%3}, {%4,%5,%6,%7}, {%8,%9}, {%0,%1,%2,%3};"
                 : "+f"(c[0]), "+f"(c[1]), "+f"(c[2]), "+f"(c[3])
                 : "r"(a[0]), "r"(a[1]), "r"(a[2]), "r"(a[3]), "r"(b[0]), "r"(b[1]));
}
__device__ __forceinline__ void cp_async16(uint32_t daddr, const void* gptr) {
    asm volatile("cp.async.cg.shared.global [%0], [%1], 16;" :: "r"(daddr), "l"(gptr) : "memory");
}
#define CP_COMMIT() asm volatile("cp.async.commit_group;" ::: "memory")
#define CP_WAIT(n)  asm volatile("cp.async.wait_group %0;" :: "n"(n) : "memory")

// ---------------------------------------------------------------------------
// fp32 -> bf16 hi/lo split
// ---------------------------------------------------------------------------
__device__ __forceinline__ void cvt4(float4 v, uint2& H, uint2& L) {
    __nv_bfloat16 h0 = __float2bfloat16(v.x), h1 = __float2bfloat16(v.y);
    __nv_bfloat16 h2 = __float2bfloat16(v.z), h3 = __float2bfloat16(v.w);
    __nv_bfloat16 l0 = __float2bfloat16(v.x - __bfloat162float(h0));
    __nv_bfloat16 l1 = __float2bfloat16(v.y - __bfloat162float(h1));
    __nv_bfloat16 l2 = __float2bfloat16(v.z - __bfloat162float(h2));
    __nv_bfloat16 l3 = __float2bfloat16(v.w - __bfloat162float(h3));
    H.x = (uint32_t)__bfloat16_as_ushort(h0) | ((uint32_t)__bfloat16_as_ushort(h1) << 16);
    H.y = (uint32_t)__bfloat16_as_ushort(h2) | ((uint32_t)__bfloat16_as_ushort(h3) << 16);
    L.x = (uint32_t)__bfloat16_as_ushort(l0) | ((uint32_t)__bfloat16_as_ushort(l1) << 16);
    L.y = (uint32_t)__bfloat16_as_ushort(l2) | ((uint32_t)__bfloat16_as_ushort(l3) << 16);
}

__global__ __launch_bounds__(256) void k_cvt_x(const float4* __restrict__ src) {
    int i = blockIdx.x * 256 + threadIdx.x;
    float4 v = src[i];
    uint2 H, L; cvt4(v, H, L);
    ((uint2*)g_xhi)[i] = H;
    ((uint2*)g_xlo)[i] = L;
}

__global__ __launch_bounds__(256) void k_cvt_w(const float4* __restrict__ wq,
                                               const float4* __restrict__ wp) {
    int i = blockIdx.x * 256 + threadIdx.x;
    if (i < 196608) {
        float4 v = wq[i];
        uint2 H, L; cvt4(v, H, L);
        ((uint2*)g_wqh)[i] = H;
        ((uint2*)g_wql)[i] = L;
    } else {
        int j = i - 196608;
        float4 v = wp[j];
        uint2 H, L; cvt4(v, H, L);
        ((uint2*)g_wph)[j] = H;
        ((uint2*)g_wpl)[j] = L;
    }
}

// ---------------------------------------------------------------------------
// Split-bf16 GEMM via mma.sync: C = A @ B^T, tile 128x128, BK=64, K=512.
// Double-buffered cp.async. 8 warps, warp tile 64x32.
// mode 0: qkv projection + elu epilogue + scatter; mode 1: out projection + bias
// ---------------------------------------------------------------------------
__global__ __launch_bounds__(256) void k_gemm_mma(int mode,
                                                  const float* __restrict__ bias,
                                                  float* __restrict__ out) {
    extern __shared__ char smraw[];
    char* sm = (char*)(((uintptr_t)smraw + 1023) & ~(uintptr_t)1023);
    const uint32_t sb = smem_u32(sm);

    const int tid = threadIdx.x;
    const int wid = tid >> 5, lane = tid & 31;
    const int wm = wid >> 2, wn = wid & 3;     // warp grid 2(m) x 4(n)
    const int m0 = blockIdx.y * 128, j0 = blockIdx.x * 128;

    const __nv_bfloat16* srcs[4];
    if (mode == 0) {
        srcs[0] = g_xhi + (size_t)m0 * 512; srcs[1] = g_xlo + (size_t)m0 * 512;
        srcs[2] = g_wqh + (size_t)j0 * 512; srcs[3] = g_wql + (size_t)j0 * 512;
    } else {
        srcs[0] = g_ohi + (size_t)m0 * 512; srcs[1] = g_olo + (size_t)m0 * 512;
        srcs[2] = g_wph + (size_t)j0 * 512; srcs[3] = g_wpl + (size_t)j0 * 512;
    }

    // per-thread fill coords: 4 iters x (row=f>>3, seg=f&7), 16B each
    const int frow[4] = { (tid + 0) >> 3, (tid + 256) >> 3, (tid + 512) >> 3, (tid + 768) >> 3 };
    const int fseg = tid & 7;

#define ISSUE(buf, kc) do {                                                        \
    _Pragma("unroll")                                                              \
    for (int t4 = 0; t4 < 4; t4++) {                                               \
        const __nv_bfloat16* s_ = srcs[t4];                                        \
        _Pragma("unroll")                                                          \
        for (int it = 0; it < 4; it++) {                                           \
            int row = frow[it];                                                    \
            uint32_t d_ = sb + (buf) * 65536 + t4 * 16384 + SWZ(row * 128 + fseg * 16); \
            cp_async16(d_, s_ + (size_t)row * 512 + (kc) * 64 + fseg * 8);         \
        }                                                                          \
    }                                                                              \
    CP_COMMIT();                                                                   \
} while (0)

    float acc[4][4][4];
#pragma unroll
    for (int i = 0; i < 4; i++)
#pragma unroll
        for (int j = 0; j < 4; j++)
#pragma unroll
            for (int c = 0; c < 4; c++) acc[i][j][c] = 0.f;

    // ldmatrix per-thread row offsets (bytes, pre-swizzle)
    const int a_r = (lane & 15);          // row within m16
    const int a_h = (lane >> 4) * 16;     // k half byte offset
    const int b_r = (lane & 7);           // row within n8
    const int b_h = ((lane >> 3) & 1) * 16;

    ISSUE(0, 0);
    for (int kc = 0; kc < 8; kc++) {
        if (kc < 7) ISSUE((kc + 1) & 1, kc + 1);
        if (kc < 7) { CP_WAIT(1); } else { CP_WAIT(0); }
        __syncthreads();

        const uint32_t base = sb + (kc & 1) * 65536;
#pragma unroll
        for (int ks = 0; ks < 4; ks++) {
            uint32_t Ah[4][4], Al[4][4], Bh[4][2], Bl[4][2];
#pragma unroll
            for (int i = 0; i < 4; i++) {
                uint32_t off = (uint32_t)((wm * 64 + i * 16 + a_r) * 128 + ks * 32 + a_h);
                ldsm_x4(Ah[i], base + SWZ(off));
                ldsm_x4(Al[i], base + 16384 + SWZ(off));
            }
#pragma unroll
            for (int j = 0; j < 4; j++) {
                uint32_t off = (uint32_t)((wn * 32 + j * 8 + b_r) * 128 + ks * 32 + b_h);
                ldsm_x2(Bh[j], base + 32768 + SWZ(off));
                ldsm_x2(Bl[j], base + 49152 + SWZ(off));
            }
#pragma unroll
            for (int i = 0; i < 4; i++)
#pragma unroll
                for (int j = 0; j < 4; j++) {
                    mma16816(acc[i][j], Ah[i], Bh[j]);
                    mma16816(acc[i][j], Ah[i], Bl[j]);
                    mma16816(acc[i][j], Al[i], Bh[j]);
                }
        }
        __syncthreads();
    }
#undef ISSUE

    // Epilogue. C fragment: c0,c1 -> row lane/4, cols 2*(lane&3)+{0,1}; c2,c3 -> row+8
    const int er = lane >> 2;
    const int ec = (lane & 3) * 2;
    if (mode == 0) {
        const int p = j0 >> 9;                  // constant per CTA
#pragma unroll
        for (int i = 0; i < 4; i++) {
#pragma unroll
            for (int j = 0; j < 4; j++) {
                int col = j0 + wn * 32 + j * 8 + ec;
                int hh = (col >> 6) & 7, d0 = col & 63;
#pragma unroll
                for (int half = 0; half < 2; half++) {
                    int m = m0 + wm * 64 + i * 16 + er + half * 8;
                    int bb = m >> 13, n = m & 8191;
                    float v0 = acc[i][j][half * 2 + 0];
                    float v1 = acc[i][j][half * 2 + 1];
                    if (p < 2) {
                        v0 = (v0 > 0.f) ? (v0 + 1.f) : expf(v0);
                        v1 = (v1 > 0.f) ? (v1 + 1.f) : expf(v1);
                    }
                    float* dst = (p == 0 ? g_q : (p == 1 ? g_k : g_v))
                               + ((size_t)((bb << 3) + hh) * 8192 + n) * 64 + d0;
                    *(float2*)dst = make_float2(v0, v1);
                }
            }
        }
    } else {
#pragma unroll
        for (int i = 0; i < 4; i++) {
#pragma unroll
            for (int j = 0; j < 4; j++) {
                int col = j0 + wn * 32 + j * 8 + ec;
                float b0 = bias[col], b1 = bias[col + 1];
#pragma unroll
                for (int half = 0; half < 2; half++) {
                    int m = m0 + wm * 64 + i * 16 + er + half * 8;
                    *(float2*)(out + (size_t)m * 512 + col) =
                        make_float2(acc[i][j][half * 2 + 0] + b0,
                                    acc[i][j][half * 2 + 1] + b1);
                }
            }
        }
    }
}

// ---------------------------------------------------------------------------
// Per-chunk S = K^T V   (64x64 per (bh, chunk))
// ---------------------------------------------------------------------------
__global__ __launch_bounds__(256) void k_chunk_kv() {
    __shared__ float Ks[64][68];
    __shared__ float Vs[64][68];
    const int bh = blockIdx.y;
    const int c = blockIdx.x;
    const int tid = threadIdx.x;
    const size_t base = ((size_t)bh * 8192 + c * 64) * 64;

#pragma unroll
    for (int r = 0; r < 4; r++) {
        int f = tid + 256 * r;
        int row = f >> 4;
        int c4 = (f & 15) * 4;
        *(float4*)&Ks[row][c4] = *(const float4*)(g_k + base + (size_t)row * 64 + c4);
        *(float4*)&Vs[row][c4] = *(const float4*)(g_v + base + (size_t)row * 64 + c4);
    }
    __syncthreads();

    const int d0 = (tid & 15) * 4;
    const int e0 = (tid >> 4) * 4;
    float acc[4][4];
#pragma unroll
    for (int i = 0; i < 4; i++)
#pragma unroll
        for (int j = 0; j < 4; j++) acc[i][j] = 0.f;

#pragma unroll 8
    for (int t = 0; t < 64; t++) {
        float4 k4 = *(const float4*)&Ks[t][d0];
        float4 v4 = *(const float4*)&Vs[t][e0];
        float ka[4] = {k4.x, k4.y, k4.z, k4.w};
        float va[4] = {v4.x, v4.y, v4.z, v4.w};
#pragma unroll
        for (int i = 0; i < 4; i++)
#pragma unroll
            for (int j = 0; j < 4; j++)
                acc[i][j] = fmaf(ka[i], va[j], acc[i][j]);
    }

    float* Sp = g_s + ((size_t)bh * NCq + c) * 4096;
#pragma unroll
    for (int i = 0; i < 4; i++)
        *(float4*)&Sp[(size_t)(d0 + i) * 64 + e0] =
            make_float4(acc[i][0], acc[i][1], acc[i][2], acc[i][3]);
}

// ---------------------------------------------------------------------------
// In-place exclusive prefix sum over chunk axis
// ---------------------------------------------------------------------------
__global__ __launch_bounds__(256) void k_prefix() {
    const int bh = blockIdx.x >> 4;
    const int entry = ((blockIdx.x & 15) << 8) + threadIdx.x;
    float run = 0.f;
    size_t idx = (size_t)bh * NCq * 4096 + entry;
#pragma unroll 4
    for (int c = 0; c < NCq; c++) {
        float s = g_s[idx];
        g_s[idx] = run;
        run += s;
        idx += 4096;
    }
}

// ---------------------------------------------------------------------------
// Per-chunk attention: out = Q @ P + tril(Q K^T) @ V ; writes hi/lo bf16
// ---------------------------------------------------------------------------
__global__ __launch_bounds__(256) void k_attn() {
    extern __shared__ float smf[];
    float (*Qs)[68] = (float(*)[68])(smf);
    float (*Ks)[68] = (float(*)[68])(smf + 64 * 68);
    float (*Vs)[68] = (float(*)[68])(smf + 2 * 64 * 68);
    float (*Ps)[68] = (float(*)[68])(smf + 3 * 64 * 68);

    const int bh = blockIdx.y;
    const int c = blockIdx.x;
    const int tid = threadIdx.x;
    const int t = tid >> 2;
    const int qd = tid & 3;
    const int e0 = qd * 16;
    const size_t base = ((size_t)bh * 8192 + c * 64) * 64;
    const float* Pg = g_s + ((size_t)bh * NCq + c) * 4096;

#pragma unroll
    for (int r = 0; r < 4; r++) {
        int f = tid + 256 * r;
        int row = f >> 4;
        int c4 = (f & 15) * 4;
        *(float4*)&Qs[row][c4] = *(const float4*)(g_q + base + (size_t)row * 64 + c4);
        *(float4*)&Ks[row][c4] = *(const float4*)(g_k + base + (size_t)row * 64 + c4);
        *(float4*)&Vs[row][c4] = *(const float4*)(g_v + base + (size_t)row * 64 + c4);
        *(float4*)&Ps[row][c4] = *(const float4*)(Pg + (size_t)row * 64 + c4);
    }
    __syncthreads();

    float acc[16];
#pragma unroll
    for (int i = 0; i < 16; i++) acc[i] = 0.f;

#pragma unroll 4
    for (int d = 0; d < 64; d++) {
        float qv = Qs[t][d];
#pragma unroll
        for (int i = 0; i < 16; i += 4) {
            float4 p4 = *(const float4*)&Ps[d][e0 + i];
            acc[i + 0] = fmaf(qv, p4.x, acc[i + 0]);
            acc[i + 1] = fmaf(qv, p4.y, acc[i + 1]);
            acc[i + 2] = fmaf(qv, p4.z, acc[i + 2]);
            acc[i + 3] = fmaf(qv, p4.w, acc[i + 3]);
        }
    }

    float qp[16];
#pragma unroll
    for (int i = 0; i < 16; i++) qp[i] = Qs[t][e0 + i];

    for (int s = 0; s < 64; s++) {
        float w = 0.f;
#pragma unroll
        for (int i = 0; i < 16; i += 4) {
            float4 k4 = *(const float4*)&Ks[s][e0 + i];
            w = fmaf(qp[i + 0], k4.x, w);
            w = fmaf(qp[i + 1], k4.y, w);
            w = fmaf(qp[i + 2], k4.z, w);
            w = fmaf(qp[i + 3], k4.w, w);
        }
        w += __shfl_xor_sync(0xffffffffu, w, 1);
        w += __shfl_xor_sync(0xffffffffu, w, 2);
        if (s > t) w = 0.f;
#pragma unroll
        for (int i = 0; i < 16; i += 4) {
            float4 v4 = *(const float4*)&Vs[s][e0 + i];
            acc[i + 0] = fmaf(w, v4.x, acc[i + 0]);
            acc[i + 1] = fmaf(w, v4.y, acc[i + 1]);
            acc[i + 2] = fmaf(w, v4.z, acc[i + 2]);
            acc[i + 3] = fmaf(w, v4.w, acc[i + 3]);
        }
    }

    __align__(16) __nv_bfloat16 hv[16];
    __align__(16) __nv_bfloat16 lv[16];
#pragma unroll
    for (int i = 0; i < 16; i++) {
        float v = acc[i];
        __nv_bfloat16 hb = __float2bfloat16(v);
        hv[i] = hb;
        lv[i] = __float2bfloat16(v - __bfloat162float(hb));
    }
    const int bb = bh >> 3;
    const int hh = bh & 7;
    const int n = c * 64 + t;
    const size_t off = ((size_t)bb * 8192 + n) * 512 + hh * 64 + e0;
    *(uint4*)(g_ohi + off)     = *(uint4*)&hv[0];
    *(uint4*)(g_ohi + off + 8) = *(uint4*)&hv[8];
    *(uint4*)(g_olo + off)     = *(uint4*)&lv[0];
    *(uint4*)(g_olo + off + 8) = *(uint4*)&lv[8];
}

// ---------------------------------------------------------------------------
extern "C" void kernel_launch(void* const* d_in, const int* in_sizes, int n_in,
                              void* d_out, int out_size) {
    const float* x     = (const float*)d_in[0];
    const float* Wqkv  = (const float*)d_in[1];
    const float* Wproj = (const float*)d_in[2];
    const float* bproj = (const float*)d_in[3];
    float* out = (float*)d_out;
    (void)in_sizes; (void)n_in; (void)out_size;

    const int gemm_smem = 2 * 65536 + 1024;
    cudaFuncSetAttribute(k_gemm_mma, cudaFuncAttributeMaxDynamicSharedMemorySize, gemm_smem);

    k_cvt_x<<<8192, 256>>>((const float4*)x);
    k_cvt_w<<<1024, 256>>>((const float4*)Wqkv, (const float4*)Wproj);

    dim3 g1(12, 128);
    k_gemm_mma<<<g1, 256, gemm_smem>>>(0, nullptr, nullptr);

    dim3 ga(NCq, BHq);
    k_chunk_kv<<<ga, 256>>>();
    k_prefix<<<256, 256>>>();

    const int attn_smem = 4 * 64 * 68 * (int)sizeof(float);
    cudaFuncSetAttribute(k_attn, cudaFuncAttributeMaxDynamicSharedMemorySize, attn_smem);
    k_attn<<<ga, 256, attn_smem>>>();

    dim3 g2(4, 128);
    k_gemm_mma<<<g2, 256, gemm_smem>>>(1, bproj, out);
}

// round 4
// speedup vs baseline: 2.9922x; 1.7576x over previous
#include <cuda_runtime.h>
#include <cuda_bf16.h>
#include <cstdint>

// Problem constants
#define Bq   2
#define Nq   8192
#define Cq   512
#define Hq   8
#define Dq   64
#define BHq  16
#define Lq   64
#define NCq  128
#define Mq   16384

// ---------------------------------------------------------------------------
// Static device scratch
// ---------------------------------------------------------------------------
__device__ float g_s[(size_t)BHq * NCq * Dq * Dq];  // per-chunk K^T V, stored TRANSPOSED [e][d]

__device__ __align__(16) __nv_bfloat16 g_qh[(size_t)BHq * Nq * Dq];
__device__ __align__(16) __nv_bfloat16 g_ql[(size_t)BHq * Nq * Dq];
__device__ __align__(16) __nv_bfloat16 g_kh[(size_t)BHq * Nq * Dq];
__device__ __align__(16) __nv_bfloat16 g_kl[(size_t)BHq * Nq * Dq];
__device__ __align__(16) __nv_bfloat16 g_vh[(size_t)BHq * Nq * Dq];
__device__ __align__(16) __nv_bfloat16 g_vl[(size_t)BHq * Nq * Dq];
__device__ __align__(16) __nv_bfloat16 g_pth[(size_t)BHq * NCq * Dq * Dq]; // exclusive prefix, [e][d]
__device__ __align__(16) __nv_bfloat16 g_ptl[(size_t)BHq * NCq * Dq * Dq];

__device__ __align__(16) __nv_bfloat16 g_xhi[(size_t)Mq * Cq];
__device__ __align__(16) __nv_bfloat16 g_xlo[(size_t)Mq * Cq];
__device__ __align__(16) __nv_bfloat16 g_wqh[1536 * 512];
__device__ __align__(16) __nv_bfloat16 g_wql[1536 * 512];
__device__ __align__(16) __nv_bfloat16 g_wph[512 * 512];
__device__ __align__(16) __nv_bfloat16 g_wpl[512 * 512];
__device__ __align__(16) __nv_bfloat16 g_ohi[(size_t)Mq * Cq];
__device__ __align__(16) __nv_bfloat16 g_olo[(size_t)Mq * Cq];

#define SWZ(o) ((o) ^ (((o) >> 3) & 0x70))

__device__ __forceinline__ uint32_t smem_u32(const void* p) {
    uint32_t a;
    asm("{ .reg .u64 t; cvta.to.shared.u64 t, %1; cvt.u32.u64 %0, t; }" : "=r"(a) : "l"(p));
    return a;
}
__device__ __forceinline__ void ldsm_x4(uint32_t* r, uint32_t addr) {
    asm volatile("ldmatrix.sync.aligned.m8n8.x4.shared.b16 {%0,%1,%2,%3}, [%4];"
                 : "=r"(r[0]), "=r"(r[1]), "=r"(r[2]), "=r"(r[3]) : "r"(addr));
}
__device__ __forceinline__ void ldsm_x4_t(uint32_t* r, uint32_t addr) {
    asm volatile("ldmatrix.sync.aligned.m8n8.x4.trans.shared.b16 {%0,%1,%2,%3}, [%4];"
                 : "=r"(r[0]), "=r"(r[1]), "=r"(r[2]), "=r"(r[3]) : "r"(addr));
}
__device__ __forceinline__ void ldsm_x2(uint32_t* r, uint32_t addr) {
    asm volatile("ldmatrix.sync.aligned.m8n8.x2.shared.b16 {%0,%1}, [%2];"
                 : "=r"(r[0]), "=r"(r[1]) : "r"(addr));
}
__device__ __forceinline__ void mma16816(float* c, const uint32_t* a, const uint32_t* b) {
    asm volatile("mma.sync.aligned.m16n8k16.row.col.f32.bf16.bf16.f32 "
                 "{%0,%1,%2,%3}, {%4,%5,%6,%7}, {%8,%9}, {%0,%1,%2,%3};"
                 : "+f"(c[0]), "+f"(c[1]), "+f"(c[2]), "+f"(c[3])
                 : "r"(a[0]), "r"(a[1]), "r"(a[2]), "r"(a[3]), "r"(b[0]), "r"(b[1]));
}
__device__ __forceinline__ void cp_async16(uint32_t daddr, const void* gptr) {
    asm volatile("cp.async.cg.shared.global [%0], [%1], 16;" :: "r"(daddr), "l"(gptr) : "memory");
}
#define CP_COMMIT() asm volatile("cp.async.commit_group;" ::: "memory")
#define CP_WAIT(n)  asm volatile("cp.async.wait_group %0;" :: "n"(n) : "memory")

// split two fp32 into hi/lo bf16x2 (packed uint32 each)
__device__ __forceinline__ void split2(float v0, float v1, uint32_t& hi, uint32_t& lo) {
    __nv_bfloat162 h = __floats2bfloat162_rn(v0, v1);
    float hx = __bfloat162float(h.x), hy = __bfloat162float(h.y);
    __nv_bfloat162 l = __floats2bfloat162_rn(v0 - hx, v1 - hy);
    hi = *(uint32_t*)&h;
    lo = *(uint32_t*)&l;
}
__device__ __forceinline__ float recon(uint32_t hi, uint32_t lo, int half) {
    __nv_bfloat162 h = *(__nv_bfloat162*)&hi;
    __nv_bfloat162 l = *(__nv_bfloat162*)&lo;
    return half ? (__bfloat162float(h.y) + __bfloat162float(l.y))
                : (__bfloat162float(h.x) + __bfloat162float(l.x));
}

// ---------------------------------------------------------------------------
// fp32 -> bf16 hi/lo split of inputs
// ---------------------------------------------------------------------------
__device__ __forceinline__ void cvt4(float4 v, uint2& H, uint2& L) {
    uint32_t h0, l0, h1, l1;
    split2(v.x, v.y, h0, l0);
    split2(v.z, v.w, h1, l1);
    H.x = h0; H.y = h1; L.x = l0; L.y = l1;
}

__global__ __launch_bounds__(256) void k_cvt_x(const float4* __restrict__ src) {
    int i = blockIdx.x * 256 + threadIdx.x;
    float4 v = src[i];
    uint2 H, L; cvt4(v, H, L);
    ((uint2*)g_xhi)[i] = H;
    ((uint2*)g_xlo)[i] = L;
}

__global__ __launch_bounds__(256) void k_cvt_w(const float4* __restrict__ wq,
                                               const float4* __restrict__ wp) {
    int i = blockIdx.x * 256 + threadIdx.x;
    if (i < 196608) {
        float4 v = wq[i];
        uint2 H, L; cvt4(v, H, L);
        ((uint2*)g_wqh)[i] = H;
        ((uint2*)g_wql)[i] = L;
    } else {
        int j = i - 196608;
        float4 v = wp[j];
        uint2 H, L; cvt4(v, H, L);
        ((uint2*)g_wph)[j] = H;
        ((uint2*)g_wpl)[j] = L;
    }
}

// ---------------------------------------------------------------------------
// Split-bf16 GEMM via mma.sync: C = A @ B^T, tile 128x128, BK=64, K=512.
// mode 0: qkv proj + elu + write bf16 hi/lo q/k/v; mode 1: out proj + bias
// ---------------------------------------------------------------------------
__global__ __launch_bounds__(256) void k_gemm_mma(int mode,
                                                  const float* __restrict__ bias,
                                                  float* __restrict__ out) {
    extern __shared__ char smraw[];
    char* sm = (char*)(((uintptr_t)smraw + 1023) & ~(uintptr_t)1023);
    const uint32_t sb = smem_u32(sm);

    const int tid = threadIdx.x;
    const int wid = tid >> 5, lane = tid & 31;
    const int wm = wid >> 2, wn = wid & 3;
    const int m0 = blockIdx.y * 128, j0 = blockIdx.x * 128;

    const __nv_bfloat16* srcs[4];
    if (mode == 0) {
        srcs[0] = g_xhi + (size_t)m0 * 512; srcs[1] = g_xlo + (size_t)m0 * 512;
        srcs[2] = g_wqh + (size_t)j0 * 512; srcs[3] = g_wql + (size_t)j0 * 512;
    } else {
        srcs[0] = g_ohi + (size_t)m0 * 512; srcs[1] = g_olo + (size_t)m0 * 512;
        srcs[2] = g_wph + (size_t)j0 * 512; srcs[3] = g_wpl + (size_t)j0 * 512;
    }

    const int frow[4] = { (tid + 0) >> 3, (tid + 256) >> 3, (tid + 512) >> 3, (tid + 768) >> 3 };
    const int fseg = tid & 7;

#define ISSUE(buf, kc) do {                                                        \
    _Pragma("unroll")                                                              \
    for (int t4 = 0; t4 < 4; t4++) {                                               \
        const __nv_bfloat16* s_ = srcs[t4];                                        \
        _Pragma("unroll")                                                          \
        for (int it = 0; it < 4; it++) {                                           \
            int row = frow[it];                                                    \
            uint32_t d_ = sb + (buf) * 65536 + t4 * 16384 + SWZ(row * 128 + fseg * 16); \
            cp_async16(d_, s_ + (size_t)row * 512 + (kc) * 64 + fseg * 8);         \
        }                                                                          \
    }                                                                              \
    CP_COMMIT();                                                                   \
} while (0)

    float acc[4][4][4];
#pragma unroll
    for (int i = 0; i < 4; i++)
#pragma unroll
        for (int j = 0; j < 4; j++)
#pragma unroll
            for (int c = 0; c < 4; c++) acc[i][j][c] = 0.f;

    const int a_r = (lane & 15);
    const int a_h = (lane >> 4) * 16;
    const int b_r = (lane & 7);
    const int b_h = ((lane >> 3) & 1) * 16;

    ISSUE(0, 0);
    for (int kc = 0; kc < 8; kc++) {
        if (kc < 7) ISSUE((kc + 1) & 1, kc + 1);
        if (kc < 7) { CP_WAIT(1); } else { CP_WAIT(0); }
        __syncthreads();

        const uint32_t base = sb + (kc & 1) * 65536;
#pragma unroll
        for (int ks = 0; ks < 4; ks++) {
            uint32_t Ah[4][4], Al[4][4], Bh[4][2], Bl[4][2];
#pragma unroll
            for (int i = 0; i < 4; i++) {
                uint32_t off = (uint32_t)((wm * 64 + i * 16 + a_r) * 128 + ks * 32 + a_h);
                ldsm_x4(Ah[i], base + SWZ(off));
                ldsm_x4(Al[i], base + 16384 + SWZ(off));
            }
#pragma unroll
            for (int j = 0; j < 4; j++) {
                uint32_t off = (uint32_t)((wn * 32 + j * 8 + b_r) * 128 + ks * 32 + b_h);
                ldsm_x2(Bh[j], base + 32768 + SWZ(off));
                ldsm_x2(Bl[j], base + 49152 + SWZ(off));
            }
#pragma unroll
            for (int i = 0; i < 4; i++)
#pragma unroll
                for (int j = 0; j < 4; j++) {
                    mma16816(acc[i][j], Ah[i], Bh[j]);
                    mma16816(acc[i][j], Ah[i], Bl[j]);
                    mma16816(acc[i][j], Al[i], Bh[j]);
                }
        }
        __syncthreads();
    }
#undef ISSUE

    const int er = lane >> 2;
    const int ec = (lane & 3) * 2;
    if (mode == 0) {
        const int p = j0 >> 9;
#pragma unroll
        for (int i = 0; i < 4; i++) {
#pragma unroll
            for (int j = 0; j < 4; j++) {
                int col = j0 + wn * 32 + j * 8 + ec;
                int hh = (col >> 6) & 7, d0 = col & 63;
#pragma unroll
                for (int half = 0; half < 2; half++) {
                    int m = m0 + wm * 64 + i * 16 + er + half * 8;
                    int bb = m >> 13, n = m & 8191;
                    float v0 = acc[i][j][half * 2 + 0];
                    float v1 = acc[i][j][half * 2 + 1];
                    if (p < 2) {
                        v0 = (v0 > 0.f) ? (v0 + 1.f) : expf(v0);
                        v1 = (v1 > 0.f) ? (v1 + 1.f) : expf(v1);
                    }
                    uint32_t hi, lo;
                    split2(v0, v1, hi, lo);
                    __nv_bfloat16* dh = (p == 0 ? g_qh : (p == 1 ? g_kh : g_vh));
                    __nv_bfloat16* dl = (p == 0 ? g_ql : (p == 1 ? g_kl : g_vl));
                    size_t off = ((size_t)((bb << 3) + hh) * 8192 + n) * 64 + d0;
                    *(uint32_t*)(dh + off) = hi;
                    *(uint32_t*)(dl + off) = lo;
                }
            }
        }
    } else {
#pragma unroll
        for (int i = 0; i < 4; i++) {
#pragma unroll
            for (int j = 0; j < 4; j++) {
                int col = j0 + wn * 32 + j * 8 + ec;
                float b0 = bias[col], b1 = bias[col + 1];
#pragma unroll
                for (int half = 0; half < 2; half++) {
                    int m = m0 + wm * 64 + i * 16 + er + half * 8;
                    *(float2*)(out + (size_t)m * 512 + col) =
                        make_float2(acc[i][j][half * 2 + 0] + b0,
                                    acc[i][j][half * 2 + 1] + b1);
                }
            }
        }
    }
}

// ---------------------------------------------------------------------------
// Per-chunk S^T = (K^T V)^T : stores St[e][d] (transposed) for prefix/QP use
// ---------------------------------------------------------------------------
__global__ __launch_bounds__(256) void k_chunk_kv() {
    __shared__ float Ks[64][68];
    __shared__ float Vs[64][68];
    const int bh = blockIdx.y;
    const int c = blockIdx.x;
    const int tid = threadIdx.x;
    const size_t base = ((size_t)bh * 8192 + c * 64) * 64;

    for (int f = tid; f < 512; f += 256) {
        int row = f >> 3, seg = f & 7;
        uint4 kh = *(const uint4*)(g_kh + base + (size_t)row * 64 + seg * 8);
        uint4 kl = *(const uint4*)(g_kl + base + (size_t)row * 64 + seg * 8);
        uint4 vh = *(const uint4*)(g_vh + base + (size_t)row * 64 + seg * 8);
        uint4 vl = *(const uint4*)(g_vl + base + (size_t)row * 64 + seg * 8);
        const uint32_t* khp = (const uint32_t*)&kh;
        const uint32_t* klp = (const uint32_t*)&kl;
        const uint32_t* vhp = (const uint32_t*)&vh;
        const uint32_t* vlp = (const uint32_t*)&vl;
#pragma unroll
        for (int q = 0; q < 4; q++) {
            Ks[row][seg * 8 + q * 2 + 0] = recon(khp[q], klp[q], 0);
            Ks[row][seg * 8 + q * 2 + 1] = recon(khp[q], klp[q], 1);
            Vs[row][seg * 8 + q * 2 + 0] = recon(vhp[q], vlp[q], 0);
            Vs[row][seg * 8 + q * 2 + 1] = recon(vhp[q], vlp[q], 1);
        }
    }
    __syncthreads();

    const int d0 = (tid & 15) * 4;
    const int e0 = (tid >> 4) * 4;
    float acc[4][4];   // acc[di][ej]
#pragma unroll
    for (int i = 0; i < 4; i++)
#pragma unroll
        for (int j = 0; j < 4; j++) acc[i][j] = 0.f;

#pragma unroll 8
    for (int t = 0; t < 64; t++) {
        float4 k4 = *(const float4*)&Ks[t][d0];
        float4 v4 = *(const float4*)&Vs[t][e0];
        float ka[4] = {k4.x, k4.y, k4.z, k4.w};
        float va[4] = {v4.x, v4.y, v4.z, v4.w};
#pragma unroll
        for (int i = 0; i < 4; i++)
#pragma unroll
            for (int j = 0; j < 4; j++)
                acc[i][j] = fmaf(ka[i], va[j], acc[i][j]);
    }

    // store transposed: St[e][d]
    float* Sp = g_s + ((size_t)bh * NCq + c) * 4096;
#pragma unroll
    for (int j = 0; j < 4; j++)
        *(float4*)&Sp[(size_t)(e0 + j) * 64 + d0] =
            make_float4(acc[0][j], acc[1][j], acc[2][j], acc[3][j]);
}

// ---------------------------------------------------------------------------
// Exclusive prefix over chunks; emit bf16 hi/lo P^T
// ---------------------------------------------------------------------------
__global__ __launch_bounds__(256) void k_prefix() {
    const int bh = blockIdx.x >> 4;
    const int entry = ((blockIdx.x & 15) << 8) + threadIdx.x;
    float run = 0.f;
    size_t idx = (size_t)bh * NCq * 4096 + entry;
#pragma unroll 4
    for (int c = 0; c < NCq; c++) {
        float s = g_s[idx];
        __nv_bfloat16 h = __float2bfloat16(run);
        g_pth[idx] = h;
        g_ptl[idx] = __float2bfloat16(run - __bfloat162float(h));
        run += s;
        idx += 4096;
    }
}

// ---------------------------------------------------------------------------
// Tensor-core per-chunk attention: out = Q@P + tril(Q K^T)@V
// 128 threads (4 warps); warp w owns output rows [w*16, w*16+16).
// smem tiles (bf16, SW128, 128B rows): Qh Ql Kh Kl Vh Vl Ph Pl  (8 x 8KB)
// ---------------------------------------------------------------------------
__global__ __launch_bounds__(128) void k_attn_mma() {
    extern __shared__ char smraw[];
    char* sm = (char*)(((uintptr_t)smraw + 1023) & ~(uintptr_t)1023);
    const uint32_t sb = smem_u32(sm);
    const int tid = threadIdx.x, lane = tid & 31, w = tid >> 5;
    const int bh = blockIdx.y, c = blockIdx.x;
    const size_t tbase = ((size_t)bh * 8192 + c * 64) * 64;
    const size_t pbase = (size_t)(bh * NCq + c) * 4096;

    const __nv_bfloat16* srcs[8] = {
        g_qh + tbase, g_ql + tbase, g_kh + tbase, g_kl + tbase,
        g_vh + tbase, g_vl + tbase, g_pth + pbase, g_ptl + pbase };
#pragma unroll
    for (int tI = 0; tI < 8; tI++) {
        const __nv_bfloat16* s = srcs[tI];
#pragma unroll
        for (int it = 0; it < 4; it++) {
            int f = tid + it * 128;
            int row = f >> 3, seg = f & 7;
            cp_async16(sb + tI * 8192 + (uint32_t)SWZ(row * 128 + seg * 16),
                       s + (size_t)row * 64 + seg * 8);
        }
    }
    CP_COMMIT(); CP_WAIT(0);
    __syncthreads();

    // fragment address helpers (byte cols pre-swizzle)
    const int aRow = w * 16 + (lane & 15);
    const int aCb  = (lane >> 4) * 16;
    const int bRow = (lane & 7) + ((lane >> 4) & 1) * 8;
    const int bCb  = ((lane >> 3) & 1) * 16;
    const int tRow = (lane & 7) + ((lane >> 3) & 1) * 8;
    const int tCb  = (lane >> 4) * 16;

#define AADDR(ofs, ks)      (sb + (ofs) + (uint32_t)SWZ(aRow * 128 + (ks) * 32 + aCb))
#define BADDR(ofs, n0, ks)  (sb + (ofs) + (uint32_t)SWZ(((n0) + bRow) * 128 + (ks) * 32 + bCb))
#define BTADDR(ofs, ks, e0) (sb + (ofs) + (uint32_t)SWZ(((ks) * 16 + tRow) * 128 + (e0) * 2 + tCb))

    float acc[8][4];
    float wac[8][4];
#pragma unroll
    for (int j = 0; j < 8; j++)
#pragma unroll
        for (int q = 0; q < 4; q++) { acc[j][q] = 0.f; wac[j][q] = 0.f; }

    // GEMM A (Q @ P) and GEMM B (W = Q K^T), sharing Q fragments per ks
#pragma unroll
    for (int ks = 0; ks < 4; ks++) {
        uint32_t Ah[4], Al[4];
        ldsm_x4(Ah, AADDR(0, ks));        // Qh
        ldsm_x4(Al, AADDR(8192, ks));     // Ql
#pragma unroll
        for (int jj = 0; jj < 4; jj++) {
            uint32_t Bh[4], Bl[4];
            ldsm_x4(Bh, BADDR(49152, jj * 16, ks));   // Ph
            ldsm_x4(Bl, BADDR(57344, jj * 16, ks));   // Pl
            mma16816(acc[2 * jj],     Ah, Bh + 0);
            mma16816(acc[2 * jj + 1], Ah, Bh + 2);
            mma16816(acc[2 * jj],     Ah, Bl + 0);
            mma16816(acc[2 * jj + 1], Ah, Bl + 2);
            mma16816(acc[2 * jj],     Al, Bh + 0);
            mma16816(acc[2 * jj + 1], Al, Bh + 2);
        }
#pragma unroll
        for (int jj = 0; jj < 4; jj++) {
            uint32_t Bh[4], Bl[4];
            ldsm_x4(Bh, BADDR(16384, jj * 16, ks));   // Kh
            ldsm_x4(Bl, BADDR(24576, jj * 16, ks));   // Kl
            mma16816(wac[2 * jj],     Ah, Bh + 0);
            mma16816(wac[2 * jj + 1], Ah, Bh + 2);
            mma16816(wac[2 * jj],     Ah, Bl + 0);
            mma16816(wac[2 * jj + 1], Ah, Bl + 2);
            mma16816(wac[2 * jj],     Al, Bh + 0);
            mma16816(wac[2 * jj + 1], Al, Bh + 2);
        }
    }

    // causal mask (inclusive diagonal): zero where s > t
    const int tr0 = w * 16 + (lane >> 2);
#pragma unroll
    for (int j = 0; j < 8; j++) {
        int s0 = j * 8 + (lane & 3) * 2;
        if (s0     > tr0)     wac[j][0] = 0.f;
        if (s0 + 1 > tr0)     wac[j][1] = 0.f;
        if (s0     > tr0 + 8) wac[j][2] = 0.f;
        if (s0 + 1 > tr0 + 8) wac[j][3] = 0.f;
    }

    // GEMM C: out += W @ V  (W hi/lo built in registers from C fragments)
#pragma unroll
    for (int ks = 0; ks < 4; ks++) {
        uint32_t Wh[4], Wl[4];
        split2(wac[2 * ks][0],     wac[2 * ks][1],     Wh[0], Wl[0]);
        split2(wac[2 * ks][2],     wac[2 * ks][3],     Wh[1], Wl[1]);
        split2(wac[2 * ks + 1][0], wac[2 * ks + 1][1], Wh[2], Wl[2]);
        split2(wac[2 * ks + 1][2], wac[2 * ks + 1][3], Wh[3], Wl[3]);
#pragma unroll
        for (int jj = 0; jj < 4; jj++) {
            uint32_t Bh[4], Bl[4];
            ldsm_x4_t(Bh, BTADDR(32768, ks, jj * 16));   // Vh (trans)
            ldsm_x4_t(Bl, BTADDR(40960, ks, jj * 16));   // Vl (trans)
            mma16816(acc[2 * jj],     Wh, Bh + 0);
            mma16816(acc[2 * jj + 1], Wh, Bh + 2);
            mma16816(acc[2 * jj],     Wh, Bl + 0);
            mma16816(acc[2 * jj + 1], Wh, Bl + 2);
            mma16816(acc[2 * jj],     Wl, Bh + 0);
            mma16816(acc[2 * jj + 1], Wl, Bh + 2);
        }
    }

    // epilogue: hi/lo bf16 to g_ohi/g_olo at [b*8192+n][h*64+e]
    const int bb = bh >> 3, hh = bh & 7;
#pragma unroll
    for (int j = 0; j < 8; j++) {
        int e = j * 8 + (lane & 3) * 2;
#pragma unroll
        for (int half = 0; half < 2; half++) {
            int t = w * 16 + (lane >> 2) + half * 8;
            int n = c * 64 + t;
            uint32_t hi, lo;
            split2(acc[j][half * 2], acc[j][half * 2 + 1], hi, lo);
            size_t off = ((size_t)bb * 8192 + n) * 512 + hh * 64 + e;
            *(uint32_t*)(g_ohi + off) = hi;
            *(uint32_t*)(g_olo + off) = lo;
        }
    }
#undef AADDR
#undef BADDR
#undef BTADDR
}

// ---------------------------------------------------------------------------
extern "C" void kernel_launch(void* const* d_in, const int* in_sizes, int n_in,
                              void* d_out, int out_size) {
    const float* x     = (const float*)d_in[0];
    const float* Wqkv  = (const float*)d_in[1];
    const float* Wproj = (const float*)d_in[2];
    const float* bproj = (const float*)d_in[3];
    float* out = (float*)d_out;
    (void)in_sizes; (void)n_in; (void)out_size;

    const int gemm_smem = 2 * 65536 + 1024;
    cudaFuncSetAttribute(k_gemm_mma, cudaFuncAttributeMaxDynamicSharedMemorySize, gemm_smem);
    const int attn_smem = 65536 + 1024;
    cudaFuncSetAttribute(k_attn_mma, cudaFuncAttributeMaxDynamicSharedMemorySize, attn_smem);

    k_cvt_x<<<8192, 256>>>((const float4*)x);
    k_cvt_w<<<1024, 256>>>((const float4*)Wqkv, (const float4*)Wproj);

    dim3 g1(12, 128);
    k_gemm_mma<<<g1, 256, gemm_smem>>>(0, nullptr, nullptr);

    dim3 ga(NCq, BHq);
    k_chunk_kv<<<ga, 256>>>();
    k_prefix<<<256, 256>>>();
    k_attn_mma<<<ga, 128, attn_smem>>>();

    dim3 g2(4, 128);
    k_gemm_mma<<<g2, 256, gemm_smem>>>(1, bproj, out);
}

// round 5
// speedup vs baseline: 3.0627x; 1.0236x over previous
#include <cuda_runtime.h>
#include <cuda_bf16.h>
#include <cstdint>

// Problem constants
#define Bq   2
#define Nq   8192
#define Cq   512
#define Hq   8
#define Dq   64
#define BHq  16
#define Lq   64
#define NCq  128
#define Mq   16384

// ---------------------------------------------------------------------------
// Static device scratch
// ---------------------------------------------------------------------------
__device__ float g_s[(size_t)BHq * NCq * Dq * Dq];  // per-chunk (K^T V)^T, [e][d]

__device__ __align__(16) __nv_bfloat16 g_qh[(size_t)BHq * Nq * Dq];
__device__ __align__(16) __nv_bfloat16 g_ql[(size_t)BHq * Nq * Dq];
__device__ __align__(16) __nv_bfloat16 g_kh[(size_t)BHq * Nq * Dq];
__device__ __align__(16) __nv_bfloat16 g_kl[(size_t)BHq * Nq * Dq];
__device__ __align__(16) __nv_bfloat16 g_vh[(size_t)BHq * Nq * Dq];
__device__ __align__(16) __nv_bfloat16 g_vl[(size_t)BHq * Nq * Dq];
__device__ __align__(16) __nv_bfloat16 g_pth[(size_t)BHq * NCq * Dq * Dq]; // exclusive prefix, [e][d]
__device__ __align__(16) __nv_bfloat16 g_ptl[(size_t)BHq * NCq * Dq * Dq];

__device__ __align__(16) __nv_bfloat16 g_xhi[(size_t)Mq * Cq];
__device__ __align__(16) __nv_bfloat16 g_xlo[(size_t)Mq * Cq];
__device__ __align__(16) __nv_bfloat16 g_wqh[1536 * 512];
__device__ __align__(16) __nv_bfloat16 g_wql[1536 * 512];
__device__ __align__(16) __nv_bfloat16 g_wph[512 * 512];
__device__ __align__(16) __nv_bfloat16 g_wpl[512 * 512];
__device__ __align__(16) __nv_bfloat16 g_ohi[(size_t)Mq * Cq];
__device__ __align__(16) __nv_bfloat16 g_olo[(size_t)Mq * Cq];

#define SWZ(o) ((o) ^ (((o) >> 3) & 0x70))

__device__ __forceinline__ uint32_t smem_u32(const void* p) {
    uint32_t a;
    asm("{ .reg .u64 t; cvta.to.shared.u64 t, %1; cvt.u32.u64 %0, t; }" : "=r"(a) : "l"(p));
    return a;
}
__device__ __forceinline__ void ldsm_x4(uint32_t* r, uint32_t addr) {
    asm volatile("ldmatrix.sync.aligned.m8n8.x4.shared.b16 {%0,%1,%2,%3}, [%4];"
                 : "=r"(r[0]), "=r"(r[1]), "=r"(r[2]), "=r"(r[3]) : "r"(addr));
}
__device__ __forceinline__ void ldsm_x4_t(uint32_t* r, uint32_t addr) {
    asm volatile("ldmatrix.sync.aligned.m8n8.x4.trans.shared.b16 {%0,%1,%2,%3}, [%4];"
                 : "=r"(r[0]), "=r"(r[1]), "=r"(r[2]), "=r"(r[3]) : "r"(addr));
}
__device__ __forceinline__ void ldsm_x2(uint32_t* r, uint32_t addr) {
    asm volatile("ldmatrix.sync.aligned.m8n8.x2.shared.b16 {%0,%1}, [%2];"
                 : "=r"(r[0]), "=r"(r[1]) : "r"(addr));
}
__device__ __forceinline__ void mma16816(float* c, const uint32_t* a, const uint32_t* b) {
    asm volatile("mma.sync.aligned.m16n8k16.row.col.f32.bf16.bf16.f32 "
                 "{%0,%1,%2,%3}, {%4,%5,%6,%7}, {%8,%9}, {%0,%1,%2,%3};"
                 : "+f"(c[0]), "+f"(c[1]), "+f"(c[2]), "+f"(c[3])
                 : "r"(a[0]), "r"(a[1]), "r"(a[2]), "r"(a[3]), "r"(b[0]), "r"(b[1]));
}
__device__ __forceinline__ void cp_async16(uint32_t daddr, const void* gptr) {
    asm volatile("cp.async.cg.shared.global [%0], [%1], 16;" :: "r"(daddr), "l"(gptr) : "memory");
}
#define CP_COMMIT() asm volatile("cp.async.commit_group;" ::: "memory")
#define CP_WAIT(n)  asm volatile("cp.async.wait_group %0;" :: "n"(n) : "memory")

// split two fp32 into hi/lo bf16x2 (packed uint32 each)
__device__ __forceinline__ void split2(float v0, float v1, uint32_t& hi, uint32_t& lo) {
    __nv_bfloat162 h = __floats2bfloat162_rn(v0, v1);
    float hx = __bfloat162float(h.x), hy = __bfloat162float(h.y);
    __nv_bfloat162 l = __floats2bfloat162_rn(v0 - hx, v1 - hy);
    hi = *(uint32_t*)&h;
    lo = *(uint32_t*)&l;
}

// ---------------------------------------------------------------------------
// fp32 -> bf16 hi/lo split of inputs
// ---------------------------------------------------------------------------
__device__ __forceinline__ void cvt4(float4 v, uint2& H, uint2& L) {
    uint32_t h0, l0, h1, l1;
    split2(v.x, v.y, h0, l0);
    split2(v.z, v.w, h1, l1);
    H.x = h0; H.y = h1; L.x = l0; L.y = l1;
}

__global__ __launch_bounds__(256) void k_cvt_x(const float4* __restrict__ src) {
    int i = blockIdx.x * 256 + threadIdx.x;
    float4 v = src[i];
    uint2 H, L; cvt4(v, H, L);
    ((uint2*)g_xhi)[i] = H;
    ((uint2*)g_xlo)[i] = L;
}

__global__ __launch_bounds__(256) void k_cvt_w(const float4* __restrict__ wq,
                                               const float4* __restrict__ wp) {
    int i = blockIdx.x * 256 + threadIdx.x;
    if (i < 196608) {
        float4 v = wq[i];
        uint2 H, L; cvt4(v, H, L);
        ((uint2*)g_wqh)[i] = H;
        ((uint2*)g_wql)[i] = L;
    } else {
        int j = i - 196608;
        float4 v = wp[j];
        uint2 H, L; cvt4(v, H, L);
        ((uint2*)g_wph)[j] = H;
        ((uint2*)g_wpl)[j] = L;
    }
}

// ---------------------------------------------------------------------------
// Split-bf16 GEMM via mma.sync: C = A @ B^T, tile 128x128, BK=64, K=512.
// 3-stage cp.async ring (prefetch depth 2). 8 warps, warp tile 64x32.
// mode 0: qkv proj + elu + write bf16 hi/lo q/k/v; mode 1: out proj + bias
// ---------------------------------------------------------------------------
__global__ __launch_bounds__(256) void k_gemm_mma(int mode,
                                                  const float* __restrict__ bias,
                                                  float* __restrict__ out) {
    extern __shared__ char smraw[];
    char* sm = (char*)(((uintptr_t)smraw + 1023) & ~(uintptr_t)1023);
    const uint32_t sb = smem_u32(sm);

    const int tid = threadIdx.x;
    const int wid = tid >> 5, lane = tid & 31;
    const int wm = wid >> 2, wn = wid & 3;
    const int m0 = blockIdx.y * 128, j0 = blockIdx.x * 128;

    const __nv_bfloat16* srcs[4];
    if (mode == 0) {
        srcs[0] = g_xhi + (size_t)m0 * 512; srcs[1] = g_xlo + (size_t)m0 * 512;
        srcs[2] = g_wqh + (size_t)j0 * 512; srcs[3] = g_wql + (size_t)j0 * 512;
    } else {
        srcs[0] = g_ohi + (size_t)m0 * 512; srcs[1] = g_olo + (size_t)m0 * 512;
        srcs[2] = g_wph + (size_t)j0 * 512; srcs[3] = g_wpl + (size_t)j0 * 512;
    }

    const int frow[4] = { (tid + 0) >> 3, (tid + 256) >> 3, (tid + 512) >> 3, (tid + 768) >> 3 };
    const int fseg = tid & 7;

#define ISSUE(buf, kc) do {                                                        \
    _Pragma("unroll")                                                              \
    for (int t4 = 0; t4 < 4; t4++) {                                               \
        const __nv_bfloat16* s_ = srcs[t4];                                        \
        _Pragma("unroll")                                                          \
        for (int it = 0; it < 4; it++) {                                           \
            int row = frow[it];                                                    \
            uint32_t d_ = sb + (buf) * 65536 + t4 * 16384 + SWZ(row * 128 + fseg * 16); \
            cp_async16(d_, s_ + (size_t)row * 512 + (kc) * 64 + fseg * 8);         \
        }                                                                          \
    }                                                                              \
    CP_COMMIT();                                                                   \
} while (0)

    float acc[4][4][4];
#pragma unroll
    for (int i = 0; i < 4; i++)
#pragma unroll
        for (int j = 0; j < 4; j++)
#pragma unroll
            for (int c = 0; c < 4; c++) acc[i][j][c] = 0.f;

    const int a_r = (lane & 15);
    const int a_h = (lane >> 4) * 16;
    const int b_r = (lane & 7);
    const int b_h = ((lane >> 3) & 1) * 16;

    ISSUE(0, 0);
    ISSUE(1, 1);
    for (int kc = 0; kc < 8; kc++) {
        if (kc + 2 < 8) {
            int b2 = (kc + 2) % 3;
            ISSUE(b2, kc + 2);
        } else {
            CP_COMMIT();        // empty group keeps wait-count arithmetic uniform
        }
        CP_WAIT(2);             // group kc complete; kc+1, kc+2 in flight
        __syncthreads();

        const uint32_t base = sb + (kc % 3) * 65536;
#pragma unroll
        for (int ks = 0; ks < 4; ks++) {
            uint32_t Ah[4][4], Al[4][4], Bh[4][2], Bl[4][2];
#pragma unroll
            for (int i = 0; i < 4; i++) {
                uint32_t off = (uint32_t)((wm * 64 + i * 16 + a_r) * 128 + ks * 32 + a_h);
                ldsm_x4(Ah[i], base + SWZ(off));
                ldsm_x4(Al[i], base + 16384 + SWZ(off));
            }
#pragma unroll
            for (int j = 0; j < 4; j++) {
                uint32_t off = (uint32_t)((wn * 32 + j * 8 + b_r) * 128 + ks * 32 + b_h);
                ldsm_x2(Bh[j], base + 32768 + SWZ(off));
                ldsm_x2(Bl[j], base + 49152 + SWZ(off));
            }
#pragma unroll
            for (int i = 0; i < 4; i++)
#pragma unroll
                for (int j = 0; j < 4; j++) {
                    mma16816(acc[i][j], Ah[i], Bh[j]);
                    mma16816(acc[i][j], Ah[i], Bl[j]);
                    mma16816(acc[i][j], Al[i], Bh[j]);
                }
        }
        __syncthreads();
    }
#undef ISSUE

    const int er = lane >> 2;
    const int ec = (lane & 3) * 2;
    if (mode == 0) {
        const int p = j0 >> 9;
#pragma unroll
        for (int i = 0; i < 4; i++) {
#pragma unroll
            for (int j = 0; j < 4; j++) {
                int col = j0 + wn * 32 + j * 8 + ec;
                int hh = (col >> 6) & 7, d0 = col & 63;
#pragma unroll
                for (int half = 0; half < 2; half++) {
                    int m = m0 + wm * 64 + i * 16 + er + half * 8;
                    int bb = m >> 13, n = m & 8191;
                    float v0 = acc[i][j][half * 2 + 0];
                    float v1 = acc[i][j][half * 2 + 1];
                    if (p < 2) {
                        v0 = (v0 > 0.f) ? (v0 + 1.f) : expf(v0);
                        v1 = (v1 > 0.f) ? (v1 + 1.f) : expf(v1);
                    }
                    uint32_t hi, lo;
                    split2(v0, v1, hi, lo);
                    __nv_bfloat16* dh = (p == 0 ? g_qh : (p == 1 ? g_kh : g_vh));
                    __nv_bfloat16* dl = (p == 0 ? g_ql : (p == 1 ? g_kl : g_vl));
                    size_t off = ((size_t)((bb << 3) + hh) * 8192 + n) * 64 + d0;
                    *(uint32_t*)(dh + off) = hi;
                    *(uint32_t*)(dl + off) = lo;
                }
            }
        }
    } else {
#pragma unroll
        for (int i = 0; i < 4; i++) {
#pragma unroll
            for (int j = 0; j < 4; j++) {
                int col = j0 + wn * 32 + j * 8 + ec;
                float b0 = bias[col], b1 = bias[col + 1];
#pragma unroll
                for (int half = 0; half < 2; half++) {
                    int m = m0 + wm * 64 + i * 16 + er + half * 8;
                    *(float2*)(out + (size_t)m * 512 + col) =
                        make_float2(acc[i][j][half * 2 + 0] + b0,
                                    acc[i][j][half * 2 + 1] + b1);
                }
            }
        }
    }
}

// ---------------------------------------------------------------------------
// Per-chunk S^T = V^T K via mma.sync (both operands ldmatrix-trans, split-bf16)
// 128 threads, warp w owns e-rows [w*16, w*16+16). Stores S^T[e][d] fp32.
// ---------------------------------------------------------------------------
__global__ __launch_bounds__(128) void k_chunk_kv() {
    __shared__ __align__(1024) char sm[32768];   // Kh, Kl, Vh, Vl tiles (8KB each)
    const uint32_t sb = smem_u32(sm);
    const int tid = threadIdx.x, lane = tid & 31, w = tid >> 5;
    const int bh = blockIdx.y, c = blockIdx.x;
    const size_t base = ((size_t)bh * 8192 + c * 64) * 64;

    const __nv_bfloat16* srcs[4] = { g_kh + base, g_kl + base, g_vh + base, g_vl + base };
#pragma unroll
    for (int tI = 0; tI < 4; tI++) {
#pragma unroll
        for (int it = 0; it < 4; it++) {
            int f = tid + it * 128;
            int row = f >> 3, seg = f & 7;
            cp_async16(sb + tI * 8192 + (uint32_t)SWZ(row * 128 + seg * 16),
                       srcs[tI] + (size_t)row * 64 + seg * 8);
        }
    }
    CP_COMMIT(); CP_WAIT(0);
    __syncthreads();

    // A = V^T (m=e), B = K^T (n=d), k = t.  trans-ldsm lane addressing:
    const int sArow = (lane & 7) + ((lane >> 4) & 1) * 8;  // k (t) within 16; bit4 = k-half
    const int sAcb  = ((lane >> 3) & 1) * 16;              // bit3 = m-half (16B)
    const int sBrow = (lane & 7) + ((lane >> 3) & 1) * 8;  // bit3 = k-half
    const int sBcb  = (lane >> 4) * 16;                    // bit4 = n-half (16B)

    float acc[8][4];
#pragma unroll
    for (int j = 0; j < 8; j++)
#pragma unroll
        for (int q = 0; q < 4; q++) acc[j][q] = 0.f;

#pragma unroll
    for (int ks = 0; ks < 4; ks++) {
        uint32_t Ah[4], Al[4];
        uint32_t aoff = (uint32_t)((ks * 16 + sArow) * 128 + w * 32 + sAcb);
        ldsm_x4_t(Ah, sb + 16384 + SWZ(aoff));   // Vh
        ldsm_x4_t(Al, sb + 24576 + SWZ(aoff));   // Vl
#pragma unroll
        for (int dg = 0; dg < 4; dg++) {
            uint32_t Bh[4], Bl[4];
            uint32_t boff = (uint32_t)((ks * 16 + sBrow) * 128 + dg * 32 + sBcb);
            ldsm_x4_t(Bh, sb + 0    + SWZ(boff));   // Kh
            ldsm_x4_t(Bl, sb + 8192 + SWZ(boff));   // Kl
            mma16816(acc[2 * dg],     Ah, Bh + 0);
            mma16816(acc[2 * dg + 1], Ah, Bh + 2);
            mma16816(acc[2 * dg],     Ah, Bl + 0);
            mma16816(acc[2 * dg + 1], Ah, Bl + 2);
            mma16816(acc[2 * dg],     Al, Bh + 0);
            mma16816(acc[2 * dg + 1], Al, Bh + 2);
        }
    }

    float* Sp = g_s + ((size_t)bh * NCq + c) * 4096;
#pragma unroll
    for (int j = 0; j < 8; j++) {
        int d = j * 8 + (lane & 3) * 2;
#pragma unroll
        for (int half = 0; half < 2; half++) {
            int e = w * 16 + (lane >> 2) + half * 8;
            *(float2*)&Sp[(size_t)e * 64 + d] =
                make_float2(acc[j][half * 2], acc[j][half * 2 + 1]);
        }
    }
}

// ---------------------------------------------------------------------------
// Exclusive prefix over chunks; emit bf16 hi/lo P^T
// ---------------------------------------------------------------------------
__global__ __launch_bounds__(256) void k_prefix() {
    const int bh = blockIdx.x >> 4;
    const int entry = ((blockIdx.x & 15) << 8) + threadIdx.x;
    float run = 0.f;
    size_t idx = (size_t)bh * NCq * 4096 + entry;
#pragma unroll 4
    for (int c = 0; c < NCq; c++) {
        float s = g_s[idx];
        __nv_bfloat16 h = __float2bfloat16(run);
        g_pth[idx] = h;
        g_ptl[idx] = __float2bfloat16(run - __bfloat162float(h));
        run += s;
        idx += 4096;
    }
}

// ---------------------------------------------------------------------------
// Tensor-core per-chunk attention: out = Q@P + tril(Q K^T)@V
// 128 threads (4 warps); warp w handles rows rw = (w + c) & 3 (load balance
// across SMSPs given the triangular skip below).
// ---------------------------------------------------------------------------
__global__ __launch_bounds__(128) void k_attn_mma() {
    extern __shared__ char smraw[];
    char* sm = (char*)(((uintptr_t)smraw + 1023) & ~(uintptr_t)1023);
    const uint32_t sb = smem_u32(sm);
    const int tid = threadIdx.x, lane = tid & 31, w = tid >> 5;
    const int bh = blockIdx.y, c = blockIdx.x;
    const int rw = (w + c) & 3;                  // rotated row-range assignment
    const size_t tbase = ((size_t)bh * 8192 + c * 64) * 64;
    const size_t pbase = (size_t)(bh * NCq + c) * 4096;

    const __nv_bfloat16* srcs[8] = {
        g_qh + tbase, g_ql + tbase, g_kh + tbase, g_kl + tbase,
        g_vh + tbase, g_vl + tbase, g_pth + pbase, g_ptl + pbase };
#pragma unroll
    for (int tI = 0; tI < 8; tI++) {
        const __nv_bfloat16* s = srcs[tI];
#pragma unroll
        for (int it = 0; it < 4; it++) {
            int f = tid + it * 128;
            int row = f >> 3, seg = f & 7;
            cp_async16(sb + tI * 8192 + (uint32_t)SWZ(row * 128 + seg * 16),
                       s + (size_t)row * 64 + seg * 8);
        }
    }
    CP_COMMIT(); CP_WAIT(0);
    __syncthreads();

    const int aRow = rw * 16 + (lane & 15);
    const int aCb  = (lane >> 4) * 16;
    const int bRow = (lane & 7) + ((lane >> 4) & 1) * 8;
    const int bCb  = ((lane >> 3) & 1) * 16;
    const int tRow = (lane & 7) + ((lane >> 3) & 1) * 8;
    const int tCb  = (lane >> 4) * 16;

#define AADDR(ofs, ks)      (sb + (ofs) + (uint32_t)SWZ(aRow * 128 + (ks) * 32 + aCb))
#define BADDR(ofs, n0, ks)  (sb + (ofs) + (uint32_t)SWZ(((n0) + bRow) * 128 + (ks) * 32 + bCb))
#define BTADDR(ofs, ks, e0) (sb + (ofs) + (uint32_t)SWZ(((ks) * 16 + tRow) * 128 + (e0) * 2 + tCb))

    float acc[8][4];
    float wac[8][4];
#pragma unroll
    for (int j = 0; j < 8; j++)
#pragma unroll
        for (int q = 0; q < 4; q++) { acc[j][q] = 0.f; wac[j][q] = 0.f; }

    // GEMM A (Q @ P, full) and GEMM B (W = Q K^T, lower-triangular tiles only)
#pragma unroll
    for (int ks = 0; ks < 4; ks++) {
        uint32_t Ah[4], Al[4];
        ldsm_x4(Ah, AADDR(0, ks));        // Qh
        ldsm_x4(Al, AADDR(8192, ks));     // Ql
#pragma unroll
        for (int jj = 0; jj < 4; jj++) {
            uint32_t Bh[4], Bl[4];
            ldsm_x4(Bh, BADDR(49152, jj * 16, ks));   // Ph
            ldsm_x4(Bl, BADDR(57344, jj * 16, ks));   // Pl
            mma16816(acc[2 * jj],     Ah, Bh + 0);
            mma16816(acc[2 * jj + 1], Ah, Bh + 2);
            mma16816(acc[2 * jj],     Ah, Bl + 0);
            mma16816(acc[2 * jj + 1], Ah, Bl + 2);
            mma16816(acc[2 * jj],     Al, Bh + 0);
            mma16816(acc[2 * jj + 1], Al, Bh + 2);
        }
#pragma unroll
        for (int jj = 0; jj < 4; jj++) {
            if (jj > rw) break;           // tiles fully above diagonal are zero
            uint32_t Bh[4], Bl[4];
            ldsm_x4(Bh, BADDR(16384, jj * 16, ks));   // Kh
            ldsm_x4(Bl, BADDR(24576, jj * 16, ks));   // Kl
            mma16816(wac[2 * jj],     Ah, Bh + 0);
            mma16816(wac[2 * jj + 1], Ah, Bh + 2);
            mma16816(wac[2 * jj],     Ah, Bl + 0);
            mma16816(wac[2 * jj + 1], Ah, Bl + 2);
            mma16816(wac[2 * jj],     Al, Bh + 0);
            mma16816(wac[2 * jj + 1], Al, Bh + 2);
        }
    }

    // causal mask (inclusive diagonal): zero where s > t
    const int tr0 = rw * 16 + (lane >> 2);
#pragma unroll
    for (int j = 0; j < 8; j++) {
        int s0 = j * 8 + (lane & 3) * 2;
        if (s0     > tr0)     wac[j][0] = 0.f;
        if (s0 + 1 > tr0)     wac[j][1] = 0.f;
        if (s0     > tr0 + 8) wac[j][2] = 0.f;
        if (s0 + 1 > tr0 + 8) wac[j][3] = 0.f;
    }

    // GEMM C: out += W @ V  (skip ks tiles with W identically zero)
#pragma unroll
    for (int ks = 0; ks < 4; ks++) {
        if (ks > rw) break;
        uint32_t Wh[4], Wl[4];
        split2(wac[2 * ks][0],     wac[2 * ks][1],     Wh[0], Wl[0]);
        split2(wac[2 * ks][2],     wac[2 * ks][3],     Wh[1], Wl[1]);
        split2(wac[2 * ks + 1][0], wac[2 * ks + 1][1], Wh[2], Wl[2]);
        split2(wac[2 * ks + 1][2], wac[2 * ks + 1][3], Wh[3], Wl[3]);
#pragma unroll
        for (int jj = 0; jj < 4; jj++) {
            uint32_t Bh[4], Bl[4];
            ldsm_x4_t(Bh, BTADDR(32768, ks, jj * 16));   // Vh (trans)
            ldsm_x4_t(Bl, BTADDR(40960, ks, jj * 16));   // Vl (trans)
            mma16816(acc[2 * jj],     Wh, Bh + 0);
            mma16816(acc[2 * jj + 1], Wh, Bh + 2);
            mma16816(acc[2 * jj],     Wh, Bl + 0);
            mma16816(acc[2 * jj + 1], Wh, Bl + 2);
            mma16816(acc[2 * jj],     Wl, Bh + 0);
            mma16816(acc[2 * jj + 1], Wl, Bh + 2);
        }
    }

    // epilogue: hi/lo bf16 to g_ohi/g_olo at [b*8192+n][h*64+e]
    const int bb = bh >> 3, hh = bh & 7;
#pragma unroll
    for (int j = 0; j < 8; j++) {
        int e = j * 8 + (lane & 3) * 2;
#pragma unroll
        for (int half = 0; half < 2; half++) {
            int t = rw * 16 + (lane >> 2) + half * 8;
            int n = c * 64 + t;
            uint32_t hi, lo;
            split2(acc[j][half * 2], acc[j][half * 2 + 1], hi, lo);
            size_t off = ((size_t)bb * 8192 + n) * 512 + hh * 64 + e;
            *(uint32_t*)(g_ohi + off) = hi;
            *(uint32_t*)(g_olo + off) = lo;
        }
    }
#undef AADDR
#undef BADDR
#undef BTADDR
}

// ---------------------------------------------------------------------------
extern "C" void kernel_launch(void* const* d_in, const int* in_sizes, int n_in,
                              void* d_out, int out_size) {
    const float* x     = (const float*)d_in[0];
    const float* Wqkv  = (const float*)d_in[1];
    const float* Wproj = (const float*)d_in[2];
    const float* bproj = (const float*)d_in[3];
    float* out = (float*)d_out;
    (void)in_sizes; (void)n_in; (void)out_size;

    const int gemm_smem = 3 * 65536 + 1024;   // 3-stage ring
    cudaFuncSetAttribute(k_gemm_mma, cudaFuncAttributeMaxDynamicSharedMemorySize, gemm_smem);
    const int attn_smem = 65536 + 1024;
    cudaFuncSetAttribute(k_attn_mma, cudaFuncAttributeMaxDynamicSharedMemorySize, attn_smem);

    k_cvt_x<<<8192, 256>>>((const float4*)x);
    k_cvt_w<<<1024, 256>>>((const float4*)Wqkv, (const float4*)Wproj);

    dim3 g1(12, 128);
    k_gemm_mma<<<g1, 256, gemm_smem>>>(0, nullptr, nullptr);

    dim3 ga(NCq, BHq);
    k_chunk_kv<<<ga, 128>>>();
    k_prefix<<<256, 256>>>();
    k_attn_mma<<<ga, 128, attn_smem>>>();

    dim3 g2(4, 128);
    k_gemm_mma<<<g2, 256, gemm_smem>>>(1, bproj, out);
}

// round 6
// speedup vs baseline: 3.2574x; 1.0636x over previous
#include <cuda_runtime.h>
#include <cuda_bf16.h>
#include <cstdint>

// Problem constants
#define Bq   2
#define Nq   8192
#define Cq   512
#define Hq   8
#define Dq   64
#define BHq  16
#define Lq   64
#define NCq  128
#define Mq   16384

// ---------------------------------------------------------------------------
// Static device scratch
// ---------------------------------------------------------------------------
__device__ __align__(16) __nv_bfloat16 g_sth[(size_t)BHq * NCq * Dq * Dq]; // per-chunk (K^T V)^T hi
__device__ __align__(16) __nv_bfloat16 g_stl[(size_t)BHq * NCq * Dq * Dq]; // lo

__device__ __align__(16) __nv_bfloat16 g_qh[(size_t)BHq * Nq * Dq];
__device__ __align__(16) __nv_bfloat16 g_ql[(size_t)BHq * Nq * Dq];
__device__ __align__(16) __nv_bfloat16 g_kh[(size_t)BHq * Nq * Dq];
__device__ __align__(16) __nv_bfloat16 g_kl[(size_t)BHq * Nq * Dq];
__device__ __align__(16) __nv_bfloat16 g_vh[(size_t)BHq * Nq * Dq];
__device__ __align__(16) __nv_bfloat16 g_vl[(size_t)BHq * Nq * Dq];
__device__ __align__(16) __nv_bfloat16 g_pth[(size_t)BHq * NCq * Dq * Dq]; // exclusive prefix, [e][d]
__device__ __align__(16) __nv_bfloat16 g_ptl[(size_t)BHq * NCq * Dq * Dq];

__device__ __align__(16) __nv_bfloat16 g_xhi[(size_t)Mq * Cq];
__device__ __align__(16) __nv_bfloat16 g_xlo[(size_t)Mq * Cq];
__device__ __align__(16) __nv_bfloat16 g_wqh[1536 * 512];
__device__ __align__(16) __nv_bfloat16 g_wql[1536 * 512];
__device__ __align__(16) __nv_bfloat16 g_wph[512 * 512];
__device__ __align__(16) __nv_bfloat16 g_wpl[512 * 512];
__device__ __align__(16) __nv_bfloat16 g_ohi[(size_t)Mq * Cq];
__device__ __align__(16) __nv_bfloat16 g_olo[(size_t)Mq * Cq];

#define SWZ(o) ((o) ^ (((o) >> 3) & 0x70))

__device__ __forceinline__ uint32_t smem_u32(const void* p) {
    uint32_t a;
    asm("{ .reg .u64 t; cvta.to.shared.u64 t, %1; cvt.u32.u64 %0, t; }" : "=r"(a) : "l"(p));
    return a;
}
__device__ __forceinline__ void ldsm_x4(uint32_t* r, uint32_t addr) {
    asm volatile("ldmatrix.sync.aligned.m8n8.x4.shared.b16 {%0,%1,%2,%3}, [%4];"
                 : "=r"(r[0]), "=r"(r[1]), "=r"(r[2]), "=r"(r[3]) : "r"(addr));
}
__device__ __forceinline__ void ldsm_x4_t(uint32_t* r, uint32_t addr) {
    asm volatile("ldmatrix.sync.aligned.m8n8.x4.trans.shared.b16 {%0,%1,%2,%3}, [%4];"
                 : "=r"(r[0]), "=r"(r[1]), "=r"(r[2]), "=r"(r[3]) : "r"(addr));
}
__device__ __forceinline__ void ldsm_x2(uint32_t* r, uint32_t addr) {
    asm volatile("ldmatrix.sync.aligned.m8n8.x2.shared.b16 {%0,%1}, [%2];"
                 : "=r"(r[0]), "=r"(r[1]) : "r"(addr));
}
__device__ __forceinline__ void mma16816(float* c, const uint32_t* a, const uint32_t* b) {
    asm volatile("mma.sync.aligned.m16n8k16.row.col.f32.bf16.bf16.f32 "
                 "{%0,%1,%2,%3}, {%4,%5,%6,%7}, {%8,%9}, {%0,%1,%2,%3};"
                 : "+f"(c[0]), "+f"(c[1]), "+f"(c[2]), "+f"(c[3])
                 : "r"(a[0]), "r"(a[1]), "r"(a[2]), "r"(a[3]), "r"(b[0]), "r"(b[1]));
}
__device__ __forceinline__ void cp_async16(uint32_t daddr, const void* gptr) {
    asm volatile("cp.async.cg.shared.global [%0], [%1], 16;" :: "r"(daddr), "l"(gptr) : "memory");
}
#define CP_COMMIT() asm volatile("cp.async.commit_group;" ::: "memory")
#define CP_WAIT(n)  asm volatile("cp.async.wait_group %0;" :: "n"(n) : "memory")

// split two fp32 into hi/lo bf16x2 (packed uint32 each)
__device__ __forceinline__ void split2(float v0, float v1, uint32_t& hi, uint32_t& lo) {
    __nv_bfloat162 h = __floats2bfloat162_rn(v0, v1);
    float hx = __bfloat162float(h.x), hy = __bfloat162float(h.y);
    __nv_bfloat162 l = __floats2bfloat162_rn(v0 - hx, v1 - hy);
    hi = *(uint32_t*)&h;
    lo = *(uint32_t*)&l;
}

// ---------------------------------------------------------------------------
// fp32 -> bf16 hi/lo split of inputs
// ---------------------------------------------------------------------------
__device__ __forceinline__ void cvt4(float4 v, uint2& H, uint2& L) {
    uint32_t h0, l0, h1, l1;
    split2(v.x, v.y, h0, l0);
    split2(v.z, v.w, h1, l1);
    H.x = h0; H.y = h1; L.x = l0; L.y = l1;
}

__global__ __launch_bounds__(256) void k_cvt_x(const float4* __restrict__ src) {
    int i = blockIdx.x * 256 + threadIdx.x;
    float4 v = src[i];
    uint2 H, L; cvt4(v, H, L);
    ((uint2*)g_xhi)[i] = H;
    ((uint2*)g_xlo)[i] = L;
}

__global__ __launch_bounds__(256) void k_cvt_w(const float4* __restrict__ wq,
                                               const float4* __restrict__ wp) {
    int i = blockIdx.x * 256 + threadIdx.x;
    if (i < 196608) {
        float4 v = wq[i];
        uint2 H, L; cvt4(v, H, L);
        ((uint2*)g_wqh)[i] = H;
        ((uint2*)g_wql)[i] = L;
    } else {
        int j = i - 196608;
        float4 v = wp[j];
        uint2 H, L; cvt4(v, H, L);
        ((uint2*)g_wph)[j] = H;
        ((uint2*)g_wpl)[j] = L;
    }
}

// ---------------------------------------------------------------------------
// Split-bf16 GEMM via mma.sync: C = A @ B^T, CTA tile 64x128, BK=64, K=512.
// 2-stage cp.async double buffer, 48KB/stage -> ~97KB smem -> 2 CTAs/SM.
// 8 warps, warp tile 32x32.
// mode 0: qkv proj + elu + write bf16 hi/lo q/k/v; mode 1: out proj + bias
// ---------------------------------------------------------------------------
#define STG 49152
__global__ __launch_bounds__(256, 2) void k_gemm_mma(int mode,
                                                     const float* __restrict__ bias,
                                                     float* __restrict__ out) {
    extern __shared__ char smraw[];
    char* sm = (char*)(((uintptr_t)smraw + 1023) & ~(uintptr_t)1023);
    const uint32_t sb = smem_u32(sm);

    const int tid = threadIdx.x;
    const int wid = tid >> 5, lane = tid & 31;
    const int wm = wid >> 2, wn = wid & 3;           // warp grid 2(m) x 4(n)
    const int m0 = blockIdx.y * 64, j0 = blockIdx.x * 128;

    const __nv_bfloat16* srcA[2];
    const __nv_bfloat16* srcB[2];
    if (mode == 0) {
        srcA[0] = g_xhi + (size_t)m0 * 512; srcA[1] = g_xlo + (size_t)m0 * 512;
        srcB[0] = g_wqh + (size_t)j0 * 512; srcB[1] = g_wql + (size_t)j0 * 512;
    } else {
        srcA[0] = g_ohi + (size_t)m0 * 512; srcA[1] = g_olo + (size_t)m0 * 512;
        srcB[0] = g_wph + (size_t)j0 * 512; srcB[1] = g_wpl + (size_t)j0 * 512;
    }

    const int fseg = tid & 7;

    // stage layout: Ah[64x128B]@0, Al@8192, Bh[128x128B]@16384, Bl@49152-16384=32768
#define ISSUE(buf, kc) do {                                                          \
    _Pragma("unroll")                                                                \
    for (int t2 = 0; t2 < 2; t2++) {                                                 \
        _Pragma("unroll")                                                            \
        for (int it = 0; it < 2; it++) {    /* A: 512 16B-chunks per tile */         \
            int f = tid + it * 256;                                                  \
            int row = f >> 3;                                                        \
            cp_async16(sb + (buf) * STG + t2 * 8192 + SWZ(row * 128 + fseg * 16),    \
                       srcA[t2] + (size_t)row * 512 + (kc) * 64 + fseg * 8);         \
        }                                                                            \
        _Pragma("unroll")                                                            \
        for (int it = 0; it < 4; it++) {    /* B: 1024 16B-chunks per tile */        \
            int f = tid + it * 256;                                                  \
            int row = f >> 3;                                                        \
            cp_async16(sb + (buf) * STG + 16384 + t2 * 16384 + SWZ(row * 128 + fseg * 16), \
                       srcB[t2] + (size_t)row * 512 + (kc) * 64 + fseg * 8);         \
        }                                                                            \
    }                                                                                \
    CP_COMMIT();                                                                     \
} while (0)

    float acc[2][4][4];
#pragma unroll
    for (int i = 0; i < 2; i++)
#pragma unroll
        for (int j = 0; j < 4; j++)
#pragma unroll
            for (int c = 0; c < 4; c++) acc[i][j][c] = 0.f;

    const int a_r = (lane & 15);
    const int a_h = (lane >> 4) * 16;
    const int b_r = (lane & 7);
    const int b_h = ((lane >> 3) & 1) * 16;

    ISSUE(0, 0);
    for (int kc = 0; kc < 8; kc++) {
        if (kc < 7) { ISSUE((kc + 1) & 1, kc + 1); CP_WAIT(1); }
        else        { CP_WAIT(0); }
        __syncthreads();

        const uint32_t base = sb + (kc & 1) * STG;
#pragma unroll
        for (int ks = 0; ks < 4; ks++) {
            uint32_t Ah[2][4], Al[2][4], Bh[4][2], Bl[4][2];
#pragma unroll
            for (int i = 0; i < 2; i++) {
                uint32_t off = (uint32_t)((wm * 32 + i * 16 + a_r) * 128 + ks * 32 + a_h);
                ldsm_x4(Ah[i], base + SWZ(off));
                ldsm_x4(Al[i], base + 8192 + SWZ(off));
            }
#pragma unroll
            for (int j = 0; j < 4; j++) {
                uint32_t off = (uint32_t)((wn * 32 + j * 8 + b_r) * 128 + ks * 32 + b_h);
                ldsm_x2(Bh[j], base + 16384 + SWZ(off));
                ldsm_x2(Bl[j], base + 32768 + SWZ(off));
            }
#pragma unroll
            for (int i = 0; i < 2; i++)
#pragma unroll
                for (int j = 0; j < 4; j++) {
                    mma16816(acc[i][j], Ah[i], Bh[j]);
                    mma16816(acc[i][j], Ah[i], Bl[j]);
                    mma16816(acc[i][j], Al[i], Bh[j]);
                }
        }
        __syncthreads();
    }
#undef ISSUE

    const int er = lane >> 2;
    const int ec = (lane & 3) * 2;
    if (mode == 0) {
        const int p = j0 >> 9;
#pragma unroll
        for (int i = 0; i < 2; i++) {
#pragma unroll
            for (int j = 0; j < 4; j++) {
                int col = j0 + wn * 32 + j * 8 + ec;
                int hh = (col >> 6) & 7, d0 = col & 63;
#pragma unroll
                for (int half = 0; half < 2; half++) {
                    int m = m0 + wm * 32 + i * 16 + er + half * 8;
                    int bb = m >> 13, n = m & 8191;
                    float v0 = acc[i][j][half * 2 + 0];
                    float v1 = acc[i][j][half * 2 + 1];
                    if (p < 2) {
                        v0 = (v0 > 0.f) ? (v0 + 1.f) : expf(v0);
                        v1 = (v1 > 0.f) ? (v1 + 1.f) : expf(v1);
                    }
                    uint32_t hi, lo;
                    split2(v0, v1, hi, lo);
                    __nv_bfloat16* dh = (p == 0 ? g_qh : (p == 1 ? g_kh : g_vh));
                    __nv_bfloat16* dl = (p == 0 ? g_ql : (p == 1 ? g_kl : g_vl));
                    size_t off = ((size_t)((bb << 3) + hh) * 8192 + n) * 64 + d0;
                    *(uint32_t*)(dh + off) = hi;
                    *(uint32_t*)(dl + off) = lo;
                }
            }
        }
    } else {
#pragma unroll
        for (int i = 0; i < 2; i++) {
#pragma unroll
            for (int j = 0; j < 4; j++) {
                int col = j0 + wn * 32 + j * 8 + ec;
                float b0 = bias[col], b1 = bias[col + 1];
#pragma unroll
                for (int half = 0; half < 2; half++) {
                    int m = m0 + wm * 32 + i * 16 + er + half * 8;
                    *(float2*)(out + (size_t)m * 512 + col) =
                        make_float2(acc[i][j][half * 2 + 0] + b0,
                                    acc[i][j][half * 2 + 1] + b1);
                }
            }
        }
    }
}
#undef STG

// ---------------------------------------------------------------------------
// Per-chunk S^T = V^T K via mma.sync; stores S^T[e][d] as bf16 hi/lo.
// ---------------------------------------------------------------------------
__global__ __launch_bounds__(128) void k_chunk_kv() {
    __shared__ __align__(1024) char sm[32768];   // Kh, Kl, Vh, Vl tiles (8KB each)
    const uint32_t sb = smem_u32(sm);
    const int tid = threadIdx.x, lane = tid & 31, w = tid >> 5;
    const int bh = blockIdx.y, c = blockIdx.x;
    const size_t base = ((size_t)bh * 8192 + c * 64) * 64;

    const __nv_bfloat16* srcs[4] = { g_kh + base, g_kl + base, g_vh + base, g_vl + base };
#pragma unroll
    for (int tI = 0; tI < 4; tI++) {
#pragma unroll
        for (int it = 0; it < 4; it++) {
            int f = tid + it * 128;
            int row = f >> 3, seg = f & 7;
            cp_async16(sb + tI * 8192 + (uint32_t)SWZ(row * 128 + seg * 16),
                       srcs[tI] + (size_t)row * 64 + seg * 8);
        }
    }
    CP_COMMIT(); CP_WAIT(0);
    __syncthreads();

    const int sArow = (lane & 7) + ((lane >> 4) & 1) * 8;
    const int sAcb  = ((lane >> 3) & 1) * 16;
    const int sBrow = (lane & 7) + ((lane >> 3) & 1) * 8;
    const int sBcb  = (lane >> 4) * 16;

    float acc[8][4];
#pragma unroll
    for (int j = 0; j < 8; j++)
#pragma unroll
        for (int q = 0; q < 4; q++) acc[j][q] = 0.f;

#pragma unroll
    for (int ks = 0; ks < 4; ks++) {
        uint32_t Ah[4], Al[4];
        uint32_t aoff = (uint32_t)((ks * 16 + sArow) * 128 + w * 32 + sAcb);
        ldsm_x4_t(Ah, sb + 16384 + SWZ(aoff));   // Vh
        ldsm_x4_t(Al, sb + 24576 + SWZ(aoff));   // Vl
#pragma unroll
        for (int dg = 0; dg < 4; dg++) {
            uint32_t Bh[4], Bl[4];
            uint32_t boff = (uint32_t)((ks * 16 + sBrow) * 128 + dg * 32 + sBcb);
            ldsm_x4_t(Bh, sb + 0    + SWZ(boff));   // Kh
            ldsm_x4_t(Bl, sb + 8192 + SWZ(boff));   // Kl
            mma16816(acc[2 * dg],     Ah, Bh + 0);
            mma16816(acc[2 * dg + 1], Ah, Bh + 2);
            mma16816(acc[2 * dg],     Ah, Bl + 0);
            mma16816(acc[2 * dg + 1], Ah, Bl + 2);
            mma16816(acc[2 * dg],     Al, Bh + 0);
            mma16816(acc[2 * dg + 1], Al, Bh + 2);
        }
    }

    __nv_bfloat16* Sh = g_sth + ((size_t)bh * NCq + c) * 4096;
    __nv_bfloat16* Sl = g_stl + ((size_t)bh * NCq + c) * 4096;
#pragma unroll
    for (int j = 0; j < 8; j++) {
        int d = j * 8 + (lane & 3) * 2;
#pragma unroll
        for (int half = 0; half < 2; half++) {
            int e = w * 16 + (lane >> 2) + half * 8;
            uint32_t hi, lo;
            split2(acc[j][half * 2], acc[j][half * 2 + 1], hi, lo);
            *(uint32_t*)(Sh + (size_t)e * 64 + d) = hi;
            *(uint32_t*)(Sl + (size_t)e * 64 + d) = lo;
        }
    }
}

// ---------------------------------------------------------------------------
// Exclusive prefix over chunks (fp32 accumulation); emit bf16 hi/lo P^T
// ---------------------------------------------------------------------------
__global__ __launch_bounds__(256) void k_prefix() {
    const int bh = blockIdx.x >> 4;
    const int entry = ((blockIdx.x & 15) << 8) + threadIdx.x;
    float run = 0.f;
    size_t idx = (size_t)bh * NCq * 4096 + entry;
#pragma unroll 4
    for (int c = 0; c < NCq; c++) {
        float s = __bfloat162float(g_sth[idx]) + __bfloat162float(g_stl[idx]);
        __nv_bfloat16 h = __float2bfloat16(run);
        g_pth[idx] = h;
        g_ptl[idx] = __float2bfloat16(run - __bfloat162float(h));
        run += s;
        idx += 4096;
    }
}

// ---------------------------------------------------------------------------
// Tensor-core per-chunk attention: out = Q@P + tril(Q K^T)@V
// ---------------------------------------------------------------------------
__global__ __launch_bounds__(128) void k_attn_mma() {
    extern __shared__ char smraw[];
    char* sm = (char*)(((uintptr_t)smraw + 1023) & ~(uintptr_t)1023);
    const uint32_t sb = smem_u32(sm);
    const int tid = threadIdx.x, lane = tid & 31, w = tid >> 5;
    const int bh = blockIdx.y, c = blockIdx.x;
    const int rw = (w + c) & 3;
    const size_t tbase = ((size_t)bh * 8192 + c * 64) * 64;
    const size_t pbase = (size_t)(bh * NCq + c) * 4096;

    const __nv_bfloat16* srcs[8] = {
        g_qh + tbase, g_ql + tbase, g_kh + tbase, g_kl + tbase,
        g_vh + tbase, g_vl + tbase, g_pth + pbase, g_ptl + pbase };
#pragma unroll
    for (int tI = 0; tI < 8; tI++) {
        const __nv_bfloat16* s = srcs[tI];
#pragma unroll
        for (int it = 0; it < 4; it++) {
            int f = tid + it * 128;
            int row = f >> 3, seg = f & 7;
            cp_async16(sb + tI * 8192 + (uint32_t)SWZ(row * 128 + seg * 16),
                       s + (size_t)row * 64 + seg * 8);
        }
    }
    CP_COMMIT(); CP_WAIT(0);
    __syncthreads();

    const int aRow = rw * 16 + (lane & 15);
    const int aCb  = (lane >> 4) * 16;
    const int bRow = (lane & 7) + ((lane >> 4) & 1) * 8;
    const int bCb  = ((lane >> 3) & 1) * 16;
    const int tRow = (lane & 7) + ((lane >> 3) & 1) * 8;
    const int tCb  = (lane >> 4) * 16;

#define AADDR(ofs, ks)      (sb + (ofs) + (uint32_t)SWZ(aRow * 128 + (ks) * 32 + aCb))
#define BADDR(ofs, n0, ks)  (sb + (ofs) + (uint32_t)SWZ(((n0) + bRow) * 128 + (ks) * 32 + bCb))
#define BTADDR(ofs, ks, e0) (sb + (ofs) + (uint32_t)SWZ(((ks) * 16 + tRow) * 128 + (e0) * 2 + tCb))

    float acc[8][4];
    float wac[8][4];
#pragma unroll
    for (int j = 0; j < 8; j++)
#pragma unroll
        for (int q = 0; q < 4; q++) { acc[j][q] = 0.f; wac[j][q] = 0.f; }

#pragma unroll
    for (int ks = 0; ks < 4; ks++) {
        uint32_t Ah[4], Al[4];
        ldsm_x4(Ah, AADDR(0, ks));        // Qh
        ldsm_x4(Al, AADDR(8192, ks));     // Ql
#pragma unroll
        for (int jj = 0; jj < 4; jj++) {
            uint32_t Bh[4], Bl[4];
            ldsm_x4(Bh, BADDR(49152, jj * 16, ks));   // Ph
            ldsm_x4(Bl, BADDR(57344, jj * 16, ks));   // Pl
            mma16816(acc[2 * jj],     Ah, Bh + 0);
            mma16816(acc[2 * jj + 1], Ah, Bh + 2);
            mma16816(acc[2 * jj],     Ah, Bl + 0);
            mma16816(acc[2 * jj + 1], Ah, Bl + 2);
            mma16816(acc[2 * jj],     Al, Bh + 0);
            mma16816(acc[2 * jj + 1], Al, Bh + 2);
        }
#pragma unroll
        for (int jj = 0; jj < 4; jj++) {
            if (jj > rw) break;
            uint32_t Bh[4], Bl[4];
            ldsm_x4(Bh, BADDR(16384, jj * 16, ks));   // Kh
            ldsm_x4(Bl, BADDR(24576, jj * 16, ks));   // Kl
            mma16816(wac[2 * jj],     Ah, Bh + 0);
            mma16816(wac[2 * jj + 1], Ah, Bh + 2);
            mma16816(wac[2 * jj],     Ah, Bl + 0);
            mma16816(wac[2 * jj + 1], Ah, Bl + 2);
            mma16816(wac[2 * jj],     Al, Bh + 0);
            mma16816(wac[2 * jj + 1], Al, Bh + 2);
        }
    }

    const int tr0 = rw * 16 + (lane >> 2);
#pragma unroll
    for (int j = 0; j < 8; j++) {
        int s0 = j * 8 + (lane & 3) * 2;
        if (s0     > tr0)     wac[j][0] = 0.f;
        if (s0 + 1 > tr0)     wac[j][1] = 0.f;
        if (s0     > tr0 + 8) wac[j][2] = 0.f;
        if (s0 + 1 > tr0 + 8) wac[j][3] = 0.f;
    }

#pragma unroll
    for (int ks = 0; ks < 4; ks++) {
        if (ks > rw) break;
        uint32_t Wh[4], Wl[4];
        split2(wac[2 * ks][0],     wac[2 * ks][1],     Wh[0], Wl[0]);
        split2(wac[2 * ks][2],     wac[2 * ks][3],     Wh[1], Wl[1]);
        split2(wac[2 * ks + 1][0], wac[2 * ks + 1][1], Wh[2], Wl[2]);
        split2(wac[2 * ks + 1][2], wac[2 * ks + 1][3], Wh[3], Wl[3]);
#pragma unroll
        for (int jj = 0; jj < 4; jj++) {
            uint32_t Bh[4], Bl[4];
            ldsm_x4_t(Bh, BTADDR(32768, ks, jj * 16));   // Vh (trans)
            ldsm_x4_t(Bl, BTADDR(40960, ks, jj * 16));   // Vl (trans)
            mma16816(acc[2 * jj],     Wh, Bh + 0);
            mma16816(acc[2 * jj + 1], Wh, Bh + 2);
            mma16816(acc[2 * jj],     Wh, Bl + 0);
            mma16816(acc[2 * jj + 1], Wh, Bl + 2);
            mma16816(acc[2 * jj],     Wl, Bh + 0);
            mma16816(acc[2 * jj + 1], Wl, Bh + 2);
        }
    }

    const int bb = bh >> 3, hh = bh & 7;
#pragma unroll
    for (int j = 0; j < 8; j++) {
        int e = j * 8 + (lane & 3) * 2;
#pragma unroll
        for (int half = 0; half < 2; half++) {
            int t = rw * 16 + (lane >> 2) + half * 8;
            int n = c * 64 + t;
            uint32_t hi, lo;
            split2(acc[j][half * 2], acc[j][half * 2 + 1], hi, lo);
            size_t off = ((size_t)bb * 8192 + n) * 512 + hh * 64 + e;
            *(uint32_t*)(g_ohi + off) = hi;
            *(uint32_t*)(g_olo + off) = lo;
        }
    }
#undef AADDR
#undef BADDR
#undef BTADDR
}

// ---------------------------------------------------------------------------
extern "C" void kernel_launch(void* const* d_in, const int* in_sizes, int n_in,
                              void* d_out, int out_size) {
    const float* x     = (const float*)d_in[0];
    const float* Wqkv  = (const float*)d_in[1];
    const float* Wproj = (const float*)d_in[2];
    const float* bproj = (const float*)d_in[3];
    float* out = (float*)d_out;
    (void)in_sizes; (void)n_in; (void)out_size;

    const int gemm_smem = 2 * 49152 + 1024;   // 2-stage, 2 CTAs/SM
    cudaFuncSetAttribute(k_gemm_mma, cudaFuncAttributeMaxDynamicSharedMemorySize, gemm_smem);
    const int attn_smem = 65536 + 1024;
    cudaFuncSetAttribute(k_attn_mma, cudaFuncAttributeMaxDynamicSharedMemorySize, attn_smem);

    k_cvt_x<<<8192, 256>>>((const float4*)x);
    k_cvt_w<<<1024, 256>>>((const float4*)Wqkv, (const float4*)Wproj);

    dim3 g1(12, 256);                        // 64-row tiles
    k_gemm_mma<<<g1, 256, gemm_smem>>>(0, nullptr, nullptr);

    dim3 ga(NCq, BHq);
    k_chunk_kv<<<ga, 128>>>();
    k_prefix<<<256, 256>>>();
    k_attn_mma<<<ga, 128, attn_smem>>>();

    dim3 g2(4, 256);
    k_gemm_mma<<<g2, 256, gemm_smem>>>(1, bproj, out);
}

// round 7
// speedup vs baseline: 4.7391x; 1.4548x over previous
#include <cuda_runtime.h>
#include <cuda_fp16.h>
#include <cstdint>

// Problem constants
#define Bq   2
#define Nq   8192
#define Cq   512
#define Hq   8
#define Dq   64
#define BHq  16
#define Lq   64
#define NCq  128
#define Mq   16384

// ---------------------------------------------------------------------------
// Static device scratch (fp16 2-term split: A-side operands keep hi+lo,
// B-side operands are hi-only)
// ---------------------------------------------------------------------------
__device__ __align__(16) __half g_sth[(size_t)BHq * NCq * Dq * Dq]; // (K^T V)^T hi
__device__ __align__(16) __half g_pth[(size_t)BHq * NCq * Dq * Dq]; // excl prefix P^T hi

__device__ __align__(16) __half g_qh[(size_t)BHq * Nq * Dq];
__device__ __align__(16) __half g_ql[(size_t)BHq * Nq * Dq];
__device__ __align__(16) __half g_kh[(size_t)BHq * Nq * Dq];        // hi only (B-side)
__device__ __align__(16) __half g_vh[(size_t)BHq * Nq * Dq];
__device__ __align__(16) __half g_vl[(size_t)BHq * Nq * Dq];

__device__ __align__(16) __half g_xh[(size_t)Mq * Cq];
__device__ __align__(16) __half g_xl[(size_t)Mq * Cq];
__device__ __align__(16) __half g_wqh[1536 * 512];                  // hi only
__device__ __align__(16) __half g_wph[512 * 512];                   // hi only
__device__ __align__(16) __half g_oh[(size_t)Mq * Cq];
__device__ __align__(16) __half g_ol[(size_t)Mq * Cq];

#define SWZ(o) ((o) ^ (((o) >> 3) & 0x70))

__device__ __forceinline__ uint32_t smem_u32(const void* p) {
    uint32_t a;
    asm("{ .reg .u64 t; cvta.to.shared.u64 t, %1; cvt.u32.u64 %0, t; }" : "=r"(a) : "l"(p));
    return a;
}
__device__ __forceinline__ void ldsm_x4(uint32_t* r, uint32_t addr) {
    asm volatile("ldmatrix.sync.aligned.m8n8.x4.shared.b16 {%0,%1,%2,%3}, [%4];"
                 : "=r"(r[0]), "=r"(r[1]), "=r"(r[2]), "=r"(r[3]) : "r"(addr));
}
__device__ __forceinline__ void ldsm_x4_t(uint32_t* r, uint32_t addr) {
    asm volatile("ldmatrix.sync.aligned.m8n8.x4.trans.shared.b16 {%0,%1,%2,%3}, [%4];"
                 : "=r"(r[0]), "=r"(r[1]), "=r"(r[2]), "=r"(r[3]) : "r"(addr));
}
__device__ __forceinline__ void ldsm_x2(uint32_t* r, uint32_t addr) {
    asm volatile("ldmatrix.sync.aligned.m8n8.x2.shared.b16 {%0,%1}, [%2];"
                 : "=r"(r[0]), "=r"(r[1]) : "r"(addr));
}
__device__ __forceinline__ void mma16816(float* c, const uint32_t* a, const uint32_t* b) {
    asm volatile("mma.sync.aligned.m16n8k16.row.col.f32.f16.f16.f32 "
                 "{%0,%1,%2,%3}, {%4,%5,%6,%7}, {%8,%9}, {%0,%1,%2,%3};"
                 : "+f"(c[0]), "+f"(c[1]), "+f"(c[2]), "+f"(c[3])
                 : "r"(a[0]), "r"(a[1]), "r"(a[2]), "r"(a[3]), "r"(b[0]), "r"(b[1]));
}
__device__ __forceinline__ void cp_async16(uint32_t daddr, const void* gptr) {
    asm volatile("cp.async.cg.shared.global [%0], [%1], 16;" :: "r"(daddr), "l"(gptr) : "memory");
}
#define CP_COMMIT() asm volatile("cp.async.commit_group;" ::: "memory")
#define CP_WAIT(n)  asm volatile("cp.async.wait_group %0;" :: "n"(n) : "memory")

// split two fp32 into fp16 hi/lo (packed half2 each)
__device__ __forceinline__ void split2h(float v0, float v1, uint32_t& hi, uint32_t& lo) {
    __half2 h = __floats2half2_rn(v0, v1);
    float hx = __low2float(h), hy = __high2float(h);
    __half2 l = __floats2half2_rn(v0 - hx, v1 - hy);
    hi = *(uint32_t*)&h;
    lo = *(uint32_t*)&l;
}
__device__ __forceinline__ uint32_t pack2h(float v0, float v1) {
    __half2 h = __floats2half2_rn(v0, v1);
    return *(uint32_t*)&h;
}

// ---------------------------------------------------------------------------
// fp32 -> fp16 conversions
// ---------------------------------------------------------------------------
__global__ __launch_bounds__(256) void k_cvt_x(const float4* __restrict__ src) {
    int i = blockIdx.x * 256 + threadIdx.x;
    float4 v = src[i];
    uint2 H, L;
    split2h(v.x, v.y, H.x, L.x);
    split2h(v.z, v.w, H.y, L.y);
    ((uint2*)g_xh)[i] = H;
    ((uint2*)g_xl)[i] = L;
}

__global__ __launch_bounds__(256) void k_cvt_w(const float4* __restrict__ wq,
                                               const float4* __restrict__ wp) {
    int i = blockIdx.x * 256 + threadIdx.x;
    if (i < 196608) {
        float4 v = wq[i];
        ((uint2*)g_wqh)[i] = make_uint2(pack2h(v.x, v.y), pack2h(v.z, v.w));
    } else {
        int j = i - 196608;
        float4 v = wp[j];
        ((uint2*)g_wph)[j] = make_uint2(pack2h(v.x, v.y), pack2h(v.z, v.w));
    }
}

// ---------------------------------------------------------------------------
// 2-term fp16 GEMM via mma.sync: C = (Ah+Al) @ Bh^T, CTA tile 64x128, BK=64.
// 2-stage cp.async, 32KB/stage -> 3 CTAs/SM. 8 warps, warp tile 32x32.
// mode 0: qkv proj + elu + store q(hi,lo) k(hi) v(hi,lo); mode 1: proj + bias
// ---------------------------------------------------------------------------
#define STG 32768
__global__ __launch_bounds__(256, 3) void k_gemm_mma(int mode,
                                                     const float* __restrict__ bias,
                                                     float* __restrict__ out) {
    extern __shared__ char smraw[];
    char* sm = (char*)(((uintptr_t)smraw + 1023) & ~(uintptr_t)1023);
    const uint32_t sb = smem_u32(sm);

    const int tid = threadIdx.x;
    const int wid = tid >> 5, lane = tid & 31;
    const int wm = wid >> 2, wn = wid & 3;           // warp grid 2(m) x 4(n)
    const int m0 = blockIdx.y * 64, j0 = blockIdx.x * 128;

    const __half* srcA[2];
    const __half* srcB;
    if (mode == 0) {
        srcA[0] = g_xh + (size_t)m0 * 512; srcA[1] = g_xl + (size_t)m0 * 512;
        srcB = g_wqh + (size_t)j0 * 512;
    } else {
        srcA[0] = g_oh + (size_t)m0 * 512; srcA[1] = g_ol + (size_t)m0 * 512;
        srcB = g_wph + (size_t)j0 * 512;
    }

    const int fseg = tid & 7;

    // stage layout: Ah[64x128B]@0, Al@8192, Bh[128x128B]@16384
#define ISSUE(buf, kc) do {                                                          \
    _Pragma("unroll")                                                                \
    for (int t2 = 0; t2 < 2; t2++) {                                                 \
        _Pragma("unroll")                                                            \
        for (int it = 0; it < 2; it++) {    /* A: 512 16B-chunks per tile */         \
            int f = tid + it * 256;                                                  \
            int row = f >> 3;                                                        \
            cp_async16(sb + (buf) * STG + t2 * 8192 + SWZ(row * 128 + fseg * 16),    \
                       srcA[t2] + (size_t)row * 512 + (kc) * 64 + fseg * 8);         \
        }                                                                            \
    }                                                                                \
    _Pragma("unroll")                                                                \
    for (int it = 0; it < 4; it++) {        /* B: 1024 16B-chunks */                 \
        int f = tid + it * 256;                                                      \
        int row = f >> 3;                                                            \
        cp_async16(sb + (buf) * STG + 16384 + SWZ(row * 128 + fseg * 16),            \
                   srcB + (size_t)row * 512 + (kc) * 64 + fseg * 8);                 \
    }                                                                                \
    CP_COMMIT();                                                                     \
} while (0)

    float acc[2][4][4];
#pragma unroll
    for (int i = 0; i < 2; i++)
#pragma unroll
        for (int j = 0; j < 4; j++)
#pragma unroll
            for (int c = 0; c < 4; c++) acc[i][j][c] = 0.f;

    const int a_r = (lane & 15);
    const int a_h = (lane >> 4) * 16;
    const int b_r = (lane & 7);
    const int b_h = ((lane >> 3) & 1) * 16;

    ISSUE(0, 0);
    for (int kc = 0; kc < 8; kc++) {
        if (kc < 7) { ISSUE((kc + 1) & 1, kc + 1); CP_WAIT(1); }
        else        { CP_WAIT(0); }
        __syncthreads();

        const uint32_t base = sb + (kc & 1) * STG;
#pragma unroll
        for (int ks = 0; ks < 4; ks++) {
            uint32_t Ah[2][4], Al[2][4], Bh[4][2];
#pragma unroll
            for (int i = 0; i < 2; i++) {
                uint32_t off = (uint32_t)((wm * 32 + i * 16 + a_r) * 128 + ks * 32 + a_h);
                ldsm_x4(Ah[i], base + SWZ(off));
                ldsm_x4(Al[i], base + 8192 + SWZ(off));
            }
#pragma unroll
            for (int j = 0; j < 4; j++) {
                uint32_t off = (uint32_t)((wn * 32 + j * 8 + b_r) * 128 + ks * 32 + b_h);
                ldsm_x2(Bh[j], base + 16384 + SWZ(off));
            }
#pragma unroll
            for (int i = 0; i < 2; i++)
#pragma unroll
                for (int j = 0; j < 4; j++) {
                    mma16816(acc[i][j], Ah[i], Bh[j]);
                    mma16816(acc[i][j], Al[i], Bh[j]);
                }
        }
        __syncthreads();
    }
#undef ISSUE

    const int er = lane >> 2;
    const int ec = (lane & 3) * 2;
    if (mode == 0) {
        const int p = j0 >> 9;
#pragma unroll
        for (int i = 0; i < 2; i++) {
#pragma unroll
            for (int j = 0; j < 4; j++) {
                int col = j0 + wn * 32 + j * 8 + ec;
                int hh = (col >> 6) & 7, d0 = col & 63;
#pragma unroll
                for (int half = 0; half < 2; half++) {
                    int m = m0 + wm * 32 + i * 16 + er + half * 8;
                    int bb = m >> 13, n = m & 8191;
                    float v0 = acc[i][j][half * 2 + 0];
                    float v1 = acc[i][j][half * 2 + 1];
                    if (p < 2) {
                        v0 = (v0 > 0.f) ? (v0 + 1.f) : expf(v0);
                        v1 = (v1 > 0.f) ? (v1 + 1.f) : expf(v1);
                    }
                    size_t off = ((size_t)((bb << 3) + hh) * 8192 + n) * 64 + d0;
                    if (p == 1) {
                        *(uint32_t*)(g_kh + off) = pack2h(v0, v1);
                    } else {
                        uint32_t hi, lo;
                        split2h(v0, v1, hi, lo);
                        __half* dh = (p == 0 ? g_qh : g_vh);
                        __half* dl = (p == 0 ? g_ql : g_vl);
                        *(uint32_t*)(dh + off) = hi;
                        *(uint32_t*)(dl + off) = lo;
                    }
                }
            }
        }
    } else {
#pragma unroll
        for (int i = 0; i < 2; i++) {
#pragma unroll
            for (int j = 0; j < 4; j++) {
                int col = j0 + wn * 32 + j * 8 + ec;
                float b0 = bias[col], b1 = bias[col + 1];
#pragma unroll
                for (int half = 0; half < 2; half++) {
                    int m = m0 + wm * 32 + i * 16 + er + half * 8;
                    *(float2*)(out + (size_t)m * 512 + col) =
                        make_float2(acc[i][j][half * 2 + 0] + b0,
                                    acc[i][j][half * 2 + 1] + b1);
                }
            }
        }
    }
}
#undef STG

// ---------------------------------------------------------------------------
// Per-chunk S^T = V^T K via mma.sync; A = V (hi+lo, trans), B = Kh (trans).
// Stores S^T[e][d] hi-only fp16.
// ---------------------------------------------------------------------------
__global__ __launch_bounds__(128) void k_chunk_kv() {
    __shared__ __align__(1024) char sm[24576];   // Kh@0, Vh@8192, Vl@16384
    const uint32_t sb = smem_u32(sm);
    const int tid = threadIdx.x, lane = tid & 31, w = tid >> 5;
    const int bh = blockIdx.y, c = blockIdx.x;
    const size_t base = ((size_t)bh * 8192 + c * 64) * 64;

    const __half* srcs[3] = { g_kh + base, g_vh + base, g_vl + base };
#pragma unroll
    for (int tI = 0; tI < 3; tI++) {
#pragma unroll
        for (int it = 0; it < 4; it++) {
            int f = tid + it * 128;
            int row = f >> 3, seg = f & 7;
            cp_async16(sb + tI * 8192 + (uint32_t)SWZ(row * 128 + seg * 16),
                       srcs[tI] + (size_t)row * 64 + seg * 8);
        }
    }
    CP_COMMIT(); CP_WAIT(0);
    __syncthreads();

    const int sArow = (lane & 7) + ((lane >> 4) & 1) * 8;
    const int sAcb  = ((lane >> 3) & 1) * 16;
    const int sBrow = (lane & 7) + ((lane >> 3) & 1) * 8;
    const int sBcb  = (lane >> 4) * 16;

    float acc[8][4];
#pragma unroll
    for (int j = 0; j < 8; j++)
#pragma unroll
        for (int q = 0; q < 4; q++) acc[j][q] = 0.f;

#pragma unroll
    for (int ks = 0; ks < 4; ks++) {
        uint32_t Ah[4], Al[4];
        uint32_t aoff = (uint32_t)((ks * 16 + sArow) * 128 + w * 32 + sAcb);
        ldsm_x4_t(Ah, sb + 8192  + SWZ(aoff));   // Vh
        ldsm_x4_t(Al, sb + 16384 + SWZ(aoff));   // Vl
#pragma unroll
        for (int dg = 0; dg < 4; dg++) {
            uint32_t Bh[4];
            uint32_t boff = (uint32_t)((ks * 16 + sBrow) * 128 + dg * 32 + sBcb);
            ldsm_x4_t(Bh, sb + SWZ(boff));       // Kh
            mma16816(acc[2 * dg],     Ah, Bh + 0);
            mma16816(acc[2 * dg + 1], Ah, Bh + 2);
            mma16816(acc[2 * dg],     Al, Bh + 0);
            mma16816(acc[2 * dg + 1], Al, Bh + 2);
        }
    }

    __half* Sh = g_sth + ((size_t)bh * NCq + c) * 4096;
#pragma unroll
    for (int j = 0; j < 8; j++) {
        int d = j * 8 + (lane & 3) * 2;
#pragma unroll
        for (int half = 0; half < 2; half++) {
            int e = w * 16 + (lane >> 2) + half * 8;
            *(uint32_t*)(Sh + (size_t)e * 64 + d) =
                pack2h(acc[j][half * 2], acc[j][half * 2 + 1]);
        }
    }
}

// ---------------------------------------------------------------------------
// Exclusive prefix over chunks (fp32 accumulation); emit fp16 P^T hi
// ---------------------------------------------------------------------------
__global__ __launch_bounds__(256) void k_prefix() {
    const int bh = blockIdx.x >> 4;
    const int entry = ((blockIdx.x & 15) << 8) + threadIdx.x;
    float run = 0.f;
    size_t idx = (size_t)bh * NCq * 4096 + entry;
#pragma unroll 4
    for (int c = 0; c < NCq; c++) {
        float s = __half2float(g_sth[idx]);
        g_pth[idx] = __float2half(run);
        run += s;
        idx += 4096;
    }
}

// ---------------------------------------------------------------------------
// Tensor-core per-chunk attention: out = Q@P + tril(Q K^T)@V
// smem: Qh@0 Ql@8192 Kh@16384 Vh@24576 Ph@32768  (5 x 8KB)
// ---------------------------------------------------------------------------
__global__ __launch_bounds__(128) void k_attn_mma() {
    extern __shared__ char smraw[];
    char* sm = (char*)(((uintptr_t)smraw + 1023) & ~(uintptr_t)1023);
    const uint32_t sb = smem_u32(sm);
    const int tid = threadIdx.x, lane = tid & 31, w = tid >> 5;
    const int bh = blockIdx.y, c = blockIdx.x;
    const int rw = (w + c) & 3;
    const size_t tbase = ((size_t)bh * 8192 + c * 64) * 64;
    const size_t pbase = (size_t)(bh * NCq + c) * 4096;

    const __half* srcs[5] = {
        g_qh + tbase, g_ql + tbase, g_kh + tbase, g_vh + tbase, g_pth + pbase };
#pragma unroll
    for (int tI = 0; tI < 5; tI++) {
        const __half* s = srcs[tI];
#pragma unroll
        for (int it = 0; it < 4; it++) {
            int f = tid + it * 128;
            int row = f >> 3, seg = f & 7;
            cp_async16(sb + tI * 8192 + (uint32_t)SWZ(row * 128 + seg * 16),
                       s + (size_t)row * 64 + seg * 8);
        }
    }
    CP_COMMIT(); CP_WAIT(0);
    __syncthreads();

    const int aRow = rw * 16 + (lane & 15);
    const int aCb  = (lane >> 4) * 16;
    const int bRow = (lane & 7) + ((lane >> 4) & 1) * 8;
    const int bCb  = ((lane >> 3) & 1) * 16;
    const int tRow = (lane & 7) + ((lane >> 3) & 1) * 8;
    const int tCb  = (lane >> 4) * 16;

#define AADDR(ofs, ks)      (sb + (ofs) + (uint32_t)SWZ(aRow * 128 + (ks) * 32 + aCb))
#define BADDR(ofs, n0, ks)  (sb + (ofs) + (uint32_t)SWZ(((n0) + bRow) * 128 + (ks) * 32 + bCb))
#define BTADDR(ofs, ks, e0) (sb + (ofs) + (uint32_t)SWZ(((ks) * 16 + tRow) * 128 + (e0) * 2 + tCb))

    float acc[8][4];
    float wac[8][4];
#pragma unroll
    for (int j = 0; j < 8; j++)
#pragma unroll
        for (int q = 0; q < 4; q++) { acc[j][q] = 0.f; wac[j][q] = 0.f; }

#pragma unroll
    for (int ks = 0; ks < 4; ks++) {
        uint32_t Ah[4], Al[4];
        ldsm_x4(Ah, AADDR(0, ks));        // Qh
        ldsm_x4(Al, AADDR(8192, ks));     // Ql
#pragma unroll
        for (int jj = 0; jj < 4; jj++) {
            uint32_t Bh[4];
            ldsm_x4(Bh, BADDR(32768, jj * 16, ks));   // Ph
            mma16816(acc[2 * jj],     Ah, Bh + 0);
            mma16816(acc[2 * jj + 1], Ah, Bh + 2);
            mma16816(acc[2 * jj],     Al, Bh + 0);
            mma16816(acc[2 * jj + 1], Al, Bh + 2);
        }
#pragma unroll
        for (int jj = 0; jj < 4; jj++) {
            if (jj > rw) break;
            uint32_t Bh[4];
            ldsm_x4(Bh, BADDR(16384, jj * 16, ks));   // Kh
            mma16816(wac[2 * jj],     Ah, Bh + 0);
            mma16816(wac[2 * jj + 1], Ah, Bh + 2);
            mma16816(wac[2 * jj],     Al, Bh + 0);
            mma16816(wac[2 * jj + 1], Al, Bh + 2);
        }
    }

    const int tr0 = rw * 16 + (lane >> 2);
#pragma unroll
    for (int j = 0; j < 8; j++) {
        int s0 = j * 8 + (lane & 3) * 2;
        if (s0     > tr0)     wac[j][0] = 0.f;
        if (s0 + 1 > tr0)     wac[j][1] = 0.f;
        if (s0     > tr0 + 8) wac[j][2] = 0.f;
        if (s0 + 1 > tr0 + 8) wac[j][3] = 0.f;
    }

#pragma unroll
    for (int ks = 0; ks < 4; ks++) {
        if (ks > rw) break;
        uint32_t Wh[4], Wl[4];
        split2h(wac[2 * ks][0],     wac[2 * ks][1],     Wh[0], Wl[0]);
        split2h(wac[2 * ks][2],     wac[2 * ks][3],     Wh[1], Wl[1]);
        split2h(wac[2 * ks + 1][0], wac[2 * ks + 1][1], Wh[2], Wl[2]);
        split2h(wac[2 * ks + 1][2], wac[2 * ks + 1][3], Wh[3], Wl[3]);
#pragma unroll
        for (int jj = 0; jj < 4; jj++) {
            uint32_t Bh[4];
            ldsm_x4_t(Bh, BTADDR(24576, ks, jj * 16));   // Vh (trans)
            mma16816(acc[2 * jj],     Wh, Bh + 0);
            mma16816(acc[2 * jj + 1], Wh, Bh + 2);
            mma16816(acc[2 * jj],     Wl, Bh + 0);
            mma16816(acc[2 * jj + 1], Wl, Bh + 2);
        }
    }

    const int bb = bh >> 3, hh = bh & 7;
#pragma unroll
    for (int j = 0; j < 8; j++) {
        int e = j * 8 + (lane & 3) * 2;
#pragma unroll
        for (int half = 0; half < 2; half++) {
            int t = rw * 16 + (lane >> 2) + half * 8;
            int n = c * 64 + t;
            uint32_t hi, lo;
            split2h(acc[j][half * 2], acc[j][half * 2 + 1], hi, lo);
            size_t off = ((size_t)bb * 8192 + n) * 512 + hh * 64 + e;
            *(uint32_t*)(g_oh + off) = hi;
            *(uint32_t*)(g_ol + off) = lo;
        }
    }
#undef AADDR
#undef BADDR
#undef BTADDR
}

// ---------------------------------------------------------------------------
extern "C" void kernel_launch(void* const* d_in, const int* in_sizes, int n_in,
                              void* d_out, int out_size) {
    const float* x     = (const float*)d_in[0];
    const float* Wqkv  = (const float*)d_in[1];
    const float* Wproj = (const float*)d_in[2];
    const float* bproj = (const float*)d_in[3];
    float* out = (float*)d_out;
    (void)in_sizes; (void)n_in; (void)out_size;

    const int gemm_smem = 2 * 32768 + 1024;   // 2-stage, 3 CTAs/SM
    cudaFuncSetAttribute(k_gemm_mma, cudaFuncAttributeMaxDynamicSharedMemorySize, gemm_smem);
    const int attn_smem = 5 * 8192 + 1024;
    cudaFuncSetAttribute(k_attn_mma, cudaFuncAttributeMaxDynamicSharedMemorySize, attn_smem);

    k_cvt_x<<<8192, 256>>>((const float4*)x);
    k_cvt_w<<<1024, 256>>>((const float4*)Wqkv, (const float4*)Wproj);

    dim3 g1(12, 256);
    k_gemm_mma<<<g1, 256, gemm_smem>>>(0, nullptr, nullptr);

    dim3 ga(NCq, BHq);
    k_chunk_kv<<<ga, 128>>>();
    k_prefix<<<256, 256>>>();
    k_attn_mma<<<ga, 128, attn_smem>>>();

    dim3 g2(4, 256);
    k_gemm_mma<<<g2, 256, gemm_smem>>>(1, bproj, out);
}

// round 8
// speedup vs baseline: 6.1833x; 1.3048x over previous
#include <cuda_runtime.h>
#include <cuda_fp16.h>
#include <cstdint>

// Problem constants
#define Bq   2
#define Nq   8192
#define Cq   512
#define Hq   8
#define Dq   64
#define BHq  16
#define Lq   64
#define NCq  128
#define Mq   16384

// ---------------------------------------------------------------------------
// Static device scratch (pure fp16, single-term)
// ---------------------------------------------------------------------------
__device__ __align__(16) __half g_sth[(size_t)BHq * NCq * Dq * Dq]; // (K^T V)^T
__device__ __align__(16) __half g_pth[(size_t)BHq * NCq * Dq * Dq]; // excl prefix P^T

__device__ __align__(16) __half g_qh[(size_t)BHq * Nq * Dq];
__device__ __align__(16) __half g_kh[(size_t)BHq * Nq * Dq];
__device__ __align__(16) __half g_vh[(size_t)BHq * Nq * Dq];

__device__ __align__(16) __half g_xh[(size_t)Mq * Cq];
__device__ __align__(16) __half g_wqh[1536 * 512];
__device__ __align__(16) __half g_wph[512 * 512];
__device__ __align__(16) __half g_oh[(size_t)Mq * Cq];

#define SWZ(o) ((o) ^ (((o) >> 3) & 0x70))

__device__ __forceinline__ uint32_t smem_u32(const void* p) {
    uint32_t a;
    asm("{ .reg .u64 t; cvta.to.shared.u64 t, %1; cvt.u32.u64 %0, t; }" : "=r"(a) : "l"(p));
    return a;
}
__device__ __forceinline__ void ldsm_x4(uint32_t* r, uint32_t addr) {
    asm volatile("ldmatrix.sync.aligned.m8n8.x4.shared.b16 {%0,%1,%2,%3}, [%4];"
                 : "=r"(r[0]), "=r"(r[1]), "=r"(r[2]), "=r"(r[3]) : "r"(addr));
}
__device__ __forceinline__ void ldsm_x4_t(uint32_t* r, uint32_t addr) {
    asm volatile("ldmatrix.sync.aligned.m8n8.x4.trans.shared.b16 {%0,%1,%2,%3}, [%4];"
                 : "=r"(r[0]), "=r"(r[1]), "=r"(r[2]), "=r"(r[3]) : "r"(addr));
}
__device__ __forceinline__ void ldsm_x2(uint32_t* r, uint32_t addr) {
    asm volatile("ldmatrix.sync.aligned.m8n8.x2.shared.b16 {%0,%1}, [%2];"
                 : "=r"(r[0]), "=r"(r[1]) : "r"(addr));
}
__device__ __forceinline__ void mma16816(float* c, const uint32_t* a, const uint32_t* b) {
    asm volatile("mma.sync.aligned.m16n8k16.row.col.f32.f16.f16.f32 "
                 "{%0,%1,%2,%3}, {%4,%5,%6,%7}, {%8,%9}, {%0,%1,%2,%3};"
                 : "+f"(c[0]), "+f"(c[1]), "+f"(c[2]), "+f"(c[3])
                 : "r"(a[0]), "r"(a[1]), "r"(a[2]), "r"(a[3]), "r"(b[0]), "r"(b[1]));
}
__device__ __forceinline__ void cp_async16(uint32_t daddr, const void* gptr) {
    asm volatile("cp.async.cg.shared.global [%0], [%1], 16;" :: "r"(daddr), "l"(gptr) : "memory");
}
#define CP_COMMIT() asm volatile("cp.async.commit_group;" ::: "memory")
#define CP_WAIT(n)  asm volatile("cp.async.wait_group %0;" :: "n"(n) : "memory")

__device__ __forceinline__ uint32_t pack2h(float v0, float v1) {
    __half2 h = __floats2half2_rn(v0, v1);
    return *(uint32_t*)&h;
}

// ---------------------------------------------------------------------------
// fp32 -> fp16 conversions
// ---------------------------------------------------------------------------
__global__ __launch_bounds__(256) void k_cvt_x(const float4* __restrict__ src) {
    int i = blockIdx.x * 256 + threadIdx.x;
    float4 v = src[i];
    ((uint2*)g_xh)[i] = make_uint2(pack2h(v.x, v.y), pack2h(v.z, v.w));
}

__global__ __launch_bounds__(256) void k_cvt_w(const float4* __restrict__ wq,
                                               const float4* __restrict__ wp) {
    int i = blockIdx.x * 256 + threadIdx.x;
    if (i < 196608) {
        float4 v = wq[i];
        ((uint2*)g_wqh)[i] = make_uint2(pack2h(v.x, v.y), pack2h(v.z, v.w));
    } else {
        int j = i - 196608;
        float4 v = wp[j];
        ((uint2*)g_wph)[j] = make_uint2(pack2h(v.x, v.y), pack2h(v.z, v.w));
    }
}

// ---------------------------------------------------------------------------
// fp16 GEMM via mma.sync: C = A @ B^T, CTA tile 64x128, BK=64, K=512.
// 2-stage cp.async, 24KB/stage -> 4 CTAs/SM. 8 warps, warp tile 32x32.
// mode 0: qkv proj + elu + store q/k/v fp16; mode 1: out proj + bias (fp32)
// ---------------------------------------------------------------------------
#define STG 24576
__global__ __launch_bounds__(256, 4) void k_gemm_mma(int mode,
                                                     const float* __restrict__ bias,
                                                     float* __restrict__ out) {
    extern __shared__ char smraw[];
    char* sm = (char*)(((uintptr_t)smraw + 1023) & ~(uintptr_t)1023);
    const uint32_t sb = smem_u32(sm);

    const int tid = threadIdx.x;
    const int wid = tid >> 5, lane = tid & 31;
    const int wm = wid >> 2, wn = wid & 3;           // warp grid 2(m) x 4(n)
    const int m0 = blockIdx.y * 64, j0 = blockIdx.x * 128;

    const __half* srcA;
    const __half* srcB;
    if (mode == 0) {
        srcA = g_xh + (size_t)m0 * 512;
        srcB = g_wqh + (size_t)j0 * 512;
    } else {
        srcA = g_oh + (size_t)m0 * 512;
        srcB = g_wph + (size_t)j0 * 512;
    }

    const int fseg = tid & 7;

    // stage layout: A[64x128B]@0, B[128x128B]@8192
#define ISSUE(buf, kc) do {                                                          \
    _Pragma("unroll")                                                                \
    for (int it = 0; it < 2; it++) {        /* A: 512 16B-chunks */                  \
        int f = tid + it * 256;                                                      \
        int row = f >> 3;                                                            \
        cp_async16(sb + (buf) * STG + SWZ(row * 128 + fseg * 16),                    \
                   srcA + (size_t)row * 512 + (kc) * 64 + fseg * 8);                 \
    }                                                                                \
    _Pragma("unroll")                                                                \
    for (int it = 0; it < 4; it++) {        /* B: 1024 16B-chunks */                 \
        int f = tid + it * 256;                                                      \
        int row = f >> 3;                                                            \
        cp_async16(sb + (buf) * STG + 8192 + SWZ(row * 128 + fseg * 16),             \
                   srcB + (size_t)row * 512 + (kc) * 64 + fseg * 8);                 \
    }                                                                                \
    CP_COMMIT();                                                                     \
} while (0)

    float acc[2][4][4];
#pragma unroll
    for (int i = 0; i < 2; i++)
#pragma unroll
        for (int j = 0; j < 4; j++)
#pragma unroll
            for (int c = 0; c < 4; c++) acc[i][j][c] = 0.f;

    const int a_r = (lane & 15);
    const int a_h = (lane >> 4) * 16;
    const int b_r = (lane & 7);
    const int b_h = ((lane >> 3) & 1) * 16;

    ISSUE(0, 0);
    for (int kc = 0; kc < 8; kc++) {
        if (kc < 7) { ISSUE((kc + 1) & 1, kc + 1); CP_WAIT(1); }
        else        { CP_WAIT(0); }
        __syncthreads();

        const uint32_t base = sb + (kc & 1) * STG;
#pragma unroll
        for (int ks = 0; ks < 4; ks++) {
            uint32_t Ah[2][4], Bh[4][2];
#pragma unroll
            for (int i = 0; i < 2; i++) {
                uint32_t off = (uint32_t)((wm * 32 + i * 16 + a_r) * 128 + ks * 32 + a_h);
                ldsm_x4(Ah[i], base + SWZ(off));
            }
#pragma unroll
            for (int j = 0; j < 4; j++) {
                uint32_t off = (uint32_t)((wn * 32 + j * 8 + b_r) * 128 + ks * 32 + b_h);
                ldsm_x2(Bh[j], base + 8192 + SWZ(off));
            }
#pragma unroll
            for (int i = 0; i < 2; i++)
#pragma unroll
                for (int j = 0; j < 4; j++)
                    mma16816(acc[i][j], Ah[i], Bh[j]);
        }
        __syncthreads();
    }
#undef ISSUE

    const int er = lane >> 2;
    const int ec = (lane & 3) * 2;
    if (mode == 0) {
        const int p = j0 >> 9;
        __half* dst = (p == 0 ? g_qh : (p == 1 ? g_kh : g_vh));
#pragma unroll
        for (int i = 0; i < 2; i++) {
#pragma unroll
            for (int j = 0; j < 4; j++) {
                int col = j0 + wn * 32 + j * 8 + ec;
                int hh = (col >> 6) & 7, d0 = col & 63;
#pragma unroll
                for (int half = 0; half < 2; half++) {
                    int m = m0 + wm * 32 + i * 16 + er + half * 8;
                    int bb = m >> 13, n = m & 8191;
                    float v0 = acc[i][j][half * 2 + 0];
                    float v1 = acc[i][j][half * 2 + 1];
                    if (p < 2) {
                        v0 = (v0 > 0.f) ? (v0 + 1.f) : expf(v0);
                        v1 = (v1 > 0.f) ? (v1 + 1.f) : expf(v1);
                    }
                    size_t off = ((size_t)((bb << 3) + hh) * 8192 + n) * 64 + d0;
                    *(uint32_t*)(dst + off) = pack2h(v0, v1);
                }
            }
        }
    } else {
#pragma unroll
        for (int i = 0; i < 2; i++) {
#pragma unroll
            for (int j = 0; j < 4; j++) {
                int col = j0 + wn * 32 + j * 8 + ec;
                float b0 = bias[col], b1 = bias[col + 1];
#pragma unroll
                for (int half = 0; half < 2; half++) {
                    int m = m0 + wm * 32 + i * 16 + er + half * 8;
                    *(float2*)(out + (size_t)m * 512 + col) =
                        make_float2(acc[i][j][half * 2 + 0] + b0,
                                    acc[i][j][half * 2 + 1] + b1);
                }
            }
        }
    }
}
#undef STG

// ---------------------------------------------------------------------------
// Per-chunk S^T = V^T K via mma.sync (A = V trans, B = K trans, fp16)
// ---------------------------------------------------------------------------
__global__ __launch_bounds__(128) void k_chunk_kv() {
    __shared__ __align__(1024) char sm[16384];   // Kh@0, Vh@8192
    const uint32_t sb = smem_u32(sm);
    const int tid = threadIdx.x, lane = tid & 31, w = tid >> 5;
    const int bh = blockIdx.y, c = blockIdx.x;
    const size_t base = ((size_t)bh * 8192 + c * 64) * 64;

    const __half* srcs[2] = { g_kh + base, g_vh + base };
#pragma unroll
    for (int tI = 0; tI < 2; tI++) {
#pragma unroll
        for (int it = 0; it < 4; it++) {
            int f = tid + it * 128;
            int row = f >> 3, seg = f & 7;
            cp_async16(sb + tI * 8192 + (uint32_t)SWZ(row * 128 + seg * 16),
                       srcs[tI] + (size_t)row * 64 + seg * 8);
        }
    }
    CP_COMMIT(); CP_WAIT(0);
    __syncthreads();

    const int sArow = (lane & 7) + ((lane >> 4) & 1) * 8;
    const int sAcb  = ((lane >> 3) & 1) * 16;
    const int sBrow = (lane & 7) + ((lane >> 3) & 1) * 8;
    const int sBcb  = (lane >> 4) * 16;

    float acc[8][4];
#pragma unroll
    for (int j = 0; j < 8; j++)
#pragma unroll
        for (int q = 0; q < 4; q++) acc[j][q] = 0.f;

#pragma unroll
    for (int ks = 0; ks < 4; ks++) {
        uint32_t Ah[4];
        uint32_t aoff = (uint32_t)((ks * 16 + sArow) * 128 + w * 32 + sAcb);
        ldsm_x4_t(Ah, sb + 8192 + SWZ(aoff));    // Vh
#pragma unroll
        for (int dg = 0; dg < 4; dg++) {
            uint32_t Bh[4];
            uint32_t boff = (uint32_t)((ks * 16 + sBrow) * 128 + dg * 32 + sBcb);
            ldsm_x4_t(Bh, sb + SWZ(boff));       // Kh
            mma16816(acc[2 * dg],     Ah, Bh + 0);
            mma16816(acc[2 * dg + 1], Ah, Bh + 2);
        }
    }

    __half* Sh = g_sth + ((size_t)bh * NCq + c) * 4096;
#pragma unroll
    for (int j = 0; j < 8; j++) {
        int d = j * 8 + (lane & 3) * 2;
#pragma unroll
        for (int half = 0; half < 2; half++) {
            int e = w * 16 + (lane >> 2) + half * 8;
            *(uint32_t*)(Sh + (size_t)e * 64 + d) =
                pack2h(acc[j][half * 2], acc[j][half * 2 + 1]);
        }
    }
}

// ---------------------------------------------------------------------------
// Exclusive prefix over chunks (fp32 accumulation); emit fp16 P^T
// ---------------------------------------------------------------------------
__global__ __launch_bounds__(256) void k_prefix() {
    const int bh = blockIdx.x >> 4;
    const int entry = ((blockIdx.x & 15) << 8) + threadIdx.x;
    float run = 0.f;
    size_t idx = (size_t)bh * NCq * 4096 + entry;
#pragma unroll 4
    for (int c = 0; c < NCq; c++) {
        float s = __half2float(g_sth[idx]);
        g_pth[idx] = __float2half(run);
        run += s;
        idx += 4096;
    }
}

// ---------------------------------------------------------------------------
// Tensor-core per-chunk attention: out = Q@P + tril(Q K^T)@V
// smem: Qh@0 Kh@8192 Vh@16384 Ph@24576  (4 x 8KB)
// ---------------------------------------------------------------------------
__global__ __launch_bounds__(128) void k_attn_mma() {
    extern __shared__ char smraw[];
    char* sm = (char*)(((uintptr_t)smraw + 1023) & ~(uintptr_t)1023);
    const uint32_t sb = smem_u32(sm);
    const int tid = threadIdx.x, lane = tid & 31, w = tid >> 5;
    const int bh = blockIdx.y, c = blockIdx.x;
    const int rw = (w + c) & 3;
    const size_t tbase = ((size_t)bh * 8192 + c * 64) * 64;
    const size_t pbase = (size_t)(bh * NCq + c) * 4096;

    const __half* srcs[4] = { g_qh + tbase, g_kh + tbase, g_vh + tbase, g_pth + pbase };
#pragma unroll
    for (int tI = 0; tI < 4; tI++) {
        const __half* s = srcs[tI];
#pragma unroll
        for (int it = 0; it < 4; it++) {
            int f = tid + it * 128;
            int row = f >> 3, seg = f & 7;
            cp_async16(sb + tI * 8192 + (uint32_t)SWZ(row * 128 + seg * 16),
                       s + (size_t)row * 64 + seg * 8);
        }
    }
    CP_COMMIT(); CP_WAIT(0);
    __syncthreads();

    const int aRow = rw * 16 + (lane & 15);
    const int aCb  = (lane >> 4) * 16;
    const int bRow = (lane & 7) + ((lane >> 4) & 1) * 8;
    const int bCb  = ((lane >> 3) & 1) * 16;
    const int tRow = (lane & 7) + ((lane >> 3) & 1) * 8;
    const int tCb  = (lane >> 4) * 16;

#define AADDR(ks)           (sb + (uint32_t)SWZ(aRow * 128 + (ks) * 32 + aCb))
#define BADDR(ofs, n0, ks)  (sb + (ofs) + (uint32_t)SWZ(((n0) + bRow) * 128 + (ks) * 32 + bCb))
#define BTADDR(ofs, ks, e0) (sb + (ofs) + (uint32_t)SWZ(((ks) * 16 + tRow) * 128 + (e0) * 2 + tCb))

    float acc[8][4];
    float wac[8][4];
#pragma unroll
    for (int j = 0; j < 8; j++)
#pragma unroll
        for (int q = 0; q < 4; q++) { acc[j][q] = 0.f; wac[j][q] = 0.f; }

#pragma unroll
    for (int ks = 0; ks < 4; ks++) {
        uint32_t Ah[4];
        ldsm_x4(Ah, AADDR(ks));           // Qh
#pragma unroll
        for (int jj = 0; jj < 4; jj++) {
            uint32_t Bh[4];
            ldsm_x4(Bh, BADDR(24576, jj * 16, ks));   // Ph
            mma16816(acc[2 * jj],     Ah, Bh + 0);
            mma16816(acc[2 * jj + 1], Ah, Bh + 2);
        }
#pragma unroll
        for (int jj = 0; jj < 4; jj++) {
            if (jj > rw) break;
            uint32_t Bh[4];
            ldsm_x4(Bh, BADDR(8192, jj * 16, ks));    // Kh
            mma16816(wac[2 * jj],     Ah, Bh + 0);
            mma16816(wac[2 * jj + 1], Ah, Bh + 2);
        }
    }

    const int tr0 = rw * 16 + (lane >> 2);
#pragma unroll
    for (int j = 0; j < 8; j++) {
        int s0 = j * 8 + (lane & 3) * 2;
        if (s0     > tr0)     wac[j][0] = 0.f;
        if (s0 + 1 > tr0)     wac[j][1] = 0.f;
        if (s0     > tr0 + 8) wac[j][2] = 0.f;
        if (s0 + 1 > tr0 + 8) wac[j][3] = 0.f;
    }

#pragma unroll
    for (int ks = 0; ks < 4; ks++) {
        if (ks > rw) break;
        uint32_t Wh[4];
        Wh[0] = pack2h(wac[2 * ks][0],     wac[2 * ks][1]);
        Wh[1] = pack2h(wac[2 * ks][2],     wac[2 * ks][3]);
        Wh[2] = pack2h(wac[2 * ks + 1][0], wac[2 * ks + 1][1]);
        Wh[3] = pack2h(wac[2 * ks + 1][2], wac[2 * ks + 1][3]);
#pragma unroll
        for (int jj = 0; jj < 4; jj++) {
            uint32_t Bh[4];
            ldsm_x4_t(Bh, BTADDR(16384, ks, jj * 16));   // Vh (trans)
            mma16816(acc[2 * jj],     Wh, Bh + 0);
            mma16816(acc[2 * jj + 1], Wh, Bh + 2);
        }
    }

    const int bb = bh >> 3, hh = bh & 7;
#pragma unroll
    for (int j = 0; j < 8; j++) {
        int e = j * 8 + (lane & 3) * 2;
#pragma unroll
        for (int half = 0; half < 2; half++) {
            int t = rw * 16 + (lane >> 2) + half * 8;
            int n = c * 64 + t;
            size_t off = ((size_t)bb * 8192 + n) * 512 + hh * 64 + e;
            *(uint32_t*)(g_oh + off) = pack2h(acc[j][half * 2], acc[j][half * 2 + 1]);
        }
    }
#undef AADDR
#undef BADDR
#undef BTADDR
}

// ---------------------------------------------------------------------------
extern "C" void kernel_launch(void* const* d_in, const int* in_sizes, int n_in,
                              void* d_out, int out_size) {
    const float* x     = (const float*)d_in[0];
    const float* Wqkv  = (const float*)d_in[1];
    const float* Wproj = (const float*)d_in[2];
    const float* bproj = (const float*)d_in[3];
    float* out = (float*)d_out;
    (void)in_sizes; (void)n_in; (void)out_size;

    const int gemm_smem = 2 * 24576 + 1024;   // 2-stage, 4 CTAs/SM
    cudaFuncSetAttribute(k_gemm_mma, cudaFuncAttributeMaxDynamicSharedMemorySize, gemm_smem);
    const int attn_smem = 4 * 8192 + 1024;
    cudaFuncSetAttribute(k_attn_mma, cudaFuncAttributeMaxDynamicSharedMemorySize, attn_smem);

    k_cvt_x<<<8192, 256>>>((const float4*)x);
    k_cvt_w<<<1024, 256>>>((const float4*)Wqkv, (const float4*)Wproj);

    dim3 g1(12, 256);
    k_gemm_mma<<<g1, 256, gemm_smem>>>(0, nullptr, nullptr);

    dim3 ga(NCq, BHq);
    k_chunk_kv<<<ga, 128>>>();
    k_prefix<<<256, 256>>>();
    k_attn_mma<<<ga, 128, attn_smem>>>();

    dim3 g2(4, 256);
    k_gemm_mma<<<g2, 256, gemm_smem>>>(1, bproj, out);
}

// round 9
// speedup vs baseline: 7.2139x; 1.1667x over previous
#include <cuda_runtime.h>
#include <cuda_fp16.h>
#include <cstdint>

// Problem constants
#define Bq   2
#define Nq   8192
#define Cq   512
#define Hq   8
#define Dq   64
#define BHq  16
#define Lq   64
#define NCq  128
#define Mq   16384

// ---------------------------------------------------------------------------
// Static device scratch (pure fp16, single-term)
// ---------------------------------------------------------------------------
__device__ __align__(16) __half g_sth[(size_t)BHq * NCq * Dq * Dq]; // (K^T V)^T
__device__ __align__(16) __half g_pth[(size_t)BHq * NCq * Dq * Dq]; // excl prefix P^T

__device__ __align__(16) __half g_qh[(size_t)BHq * Nq * Dq];
__device__ __align__(16) __half g_kh[(size_t)BHq * Nq * Dq];
__device__ __align__(16) __half g_vh[(size_t)BHq * Nq * Dq];

__device__ __align__(16) __half g_xh[(size_t)Mq * Cq];
__device__ __align__(16) __half g_wqh[1536 * 512];
__device__ __align__(16) __half g_wph[512 * 512];
__device__ __align__(16) __half g_oh[(size_t)Mq * Cq];

#define SWZ(o) ((o) ^ (((o) >> 3) & 0x70))

__device__ __forceinline__ uint32_t smem_u32(const void* p) {
    uint32_t a;
    asm("{ .reg .u64 t; cvta.to.shared.u64 t, %1; cvt.u32.u64 %0, t; }" : "=r"(a) : "l"(p));
    return a;
}
__device__ __forceinline__ void ldsm_x4(uint32_t* r, uint32_t addr) {
    asm volatile("ldmatrix.sync.aligned.m8n8.x4.shared.b16 {%0,%1,%2,%3}, [%4];"
                 : "=r"(r[0]), "=r"(r[1]), "=r"(r[2]), "=r"(r[3]) : "r"(addr));
}
__device__ __forceinline__ void ldsm_x4_t(uint32_t* r, uint32_t addr) {
    asm volatile("ldmatrix.sync.aligned.m8n8.x4.trans.shared.b16 {%0,%1,%2,%3}, [%4];"
                 : "=r"(r[0]), "=r"(r[1]), "=r"(r[2]), "=r"(r[3]) : "r"(addr));
}
__device__ __forceinline__ void ldsm_x2(uint32_t* r, uint32_t addr) {
    asm volatile("ldmatrix.sync.aligned.m8n8.x2.shared.b16 {%0,%1}, [%2];"
                 : "=r"(r[0]), "=r"(r[1]) : "r"(addr));
}
__device__ __forceinline__ void mma16816(float* c, const uint32_t* a, const uint32_t* b) {
    asm volatile("mma.sync.aligned.m16n8k16.row.col.f32.f16.f16.f32 "
                 "{%0,%1,%2,%3}, {%4,%5,%6,%7}, {%8,%9}, {%0,%1,%2,%3};"
                 : "+f"(c[0]), "+f"(c[1]), "+f"(c[2]), "+f"(c[3])
                 : "r"(a[0]), "r"(a[1]), "r"(a[2]), "r"(a[3]), "r"(b[0]), "r"(b[1]));
}
__device__ __forceinline__ void cp_async16(uint32_t daddr, const void* gptr) {
    asm volatile("cp.async.cg.shared.global [%0], [%1], 16;" :: "r"(daddr), "l"(gptr) : "memory");
}
#define CP_COMMIT() asm volatile("cp.async.commit_group;" ::: "memory")
#define CP_WAIT(n)  asm volatile("cp.async.wait_group %0;" :: "n"(n) : "memory")

__device__ __forceinline__ uint32_t pack2h(float v0, float v1) {
    __half2 h = __floats2half2_rn(v0, v1);
    return *(uint32_t*)&h;
}

// ---------------------------------------------------------------------------
// fp32 -> fp16 conversion (x, W_qkv, W_proj in one launch)
// ---------------------------------------------------------------------------
__global__ __launch_bounds__(256) void k_cvt_all(const float4* __restrict__ x,
                                                 const float4* __restrict__ wq,
                                                 const float4* __restrict__ wp) {
    int i = blockIdx.x * 256 + threadIdx.x;     // 0 .. 2359295
    if (i < 2097152) {
        float4 v = x[i];
        ((uint2*)g_xh)[i] = make_uint2(pack2h(v.x, v.y), pack2h(v.z, v.w));
    } else if (i < 2293760) {
        int j = i - 2097152;
        float4 v = wq[j];
        ((uint2*)g_wqh)[j] = make_uint2(pack2h(v.x, v.y), pack2h(v.z, v.w));
    } else {
        int j = i - 2293760;
        float4 v = wp[j];
        ((uint2*)g_wph)[j] = make_uint2(pack2h(v.x, v.y), pack2h(v.z, v.w));
    }
}

// ---------------------------------------------------------------------------
// fp16 GEMM via mma.sync: C = A @ B^T, CTA tile 128x128, BK=64, K=512.
// 2-stage cp.async, 32KB/stage -> 2 CTAs/SM, 16 warps/SM.
// 8 warps, warp tile 64x32.
// mode 0: qkv proj + elu + store q/k/v fp16; mode 1: out proj + bias (fp32)
// ---------------------------------------------------------------------------
#define STG 32768
__global__ __launch_bounds__(256, 2) void k_gemm_mma(int mode,
                                                     const float* __restrict__ bias,
                                                     float* __restrict__ out) {
    extern __shared__ char smraw[];
    char* sm = (char*)(((uintptr_t)smraw + 1023) & ~(uintptr_t)1023);
    const uint32_t sb = smem_u32(sm);

    const int tid = threadIdx.x;
    const int wid = tid >> 5, lane = tid & 31;
    const int wm = wid >> 2, wn = wid & 3;           // warp grid 2(m) x 4(n)
    const int m0 = blockIdx.y * 128, j0 = blockIdx.x * 128;

    const __half* srcA;
    const __half* srcB;
    if (mode == 0) {
        srcA = g_xh + (size_t)m0 * 512;
        srcB = g_wqh + (size_t)j0 * 512;
    } else {
        srcA = g_oh + (size_t)m0 * 512;
        srcB = g_wph + (size_t)j0 * 512;
    }

    const int fseg = tid & 7;

    // stage layout: A[128x128B]@0, B[128x128B]@16384
#define ISSUE(buf, kc) do {                                                          \
    _Pragma("unroll")                                                                \
    for (int it = 0; it < 4; it++) {        /* A: 1024 16B-chunks */                 \
        int f = tid + it * 256;                                                      \
        int row = f >> 3;                                                            \
        cp_async16(sb + (buf) * STG + SWZ(row * 128 + fseg * 16),                    \
                   srcA + (size_t)row * 512 + (kc) * 64 + fseg * 8);                 \
    }                                                                                \
    _Pragma("unroll")                                                                \
    for (int it = 0; it < 4; it++) {        /* B: 1024 16B-chunks */                 \
        int f = tid + it * 256;                                                      \
        int row = f >> 3;                                                            \
        cp_async16(sb + (buf) * STG + 16384 + SWZ(row * 128 + fseg * 16),            \
                   srcB + (size_t)row * 512 + (kc) * 64 + fseg * 8);                 \
    }                                                                                \
    CP_COMMIT();                                                                     \
} while (0)

    float acc[4][4][4];
#pragma unroll
    for (int i = 0; i < 4; i++)
#pragma unroll
        for (int j = 0; j < 4; j++)
#pragma unroll
            for (int c = 0; c < 4; c++) acc[i][j][c] = 0.f;

    const int a_r = (lane & 15);
    const int a_h = (lane >> 4) * 16;
    const int b_r = (lane & 7);
    const int b_h = ((lane >> 3) & 1) * 16;

    ISSUE(0, 0);
    for (int kc = 0; kc < 8; kc++) {
        if (kc < 7) { ISSUE((kc + 1) & 1, kc + 1); CP_WAIT(1); }
        else        { CP_WAIT(0); }
        __syncthreads();

        const uint32_t base = sb + (kc & 1) * STG;
#pragma unroll
        for (int ks = 0; ks < 4; ks++) {
            uint32_t Ah[4][4], Bh[4][2];
#pragma unroll
            for (int i = 0; i < 4; i++) {
                uint32_t off = (uint32_t)((wm * 64 + i * 16 + a_r) * 128 + ks * 32 + a_h);
                ldsm_x4(Ah[i], base + SWZ(off));
            }
#pragma unroll
            for (int j = 0; j < 4; j++) {
                uint32_t off = (uint32_t)((wn * 32 + j * 8 + b_r) * 128 + ks * 32 + b_h);
                ldsm_x2(Bh[j], base + 16384 + SWZ(off));
            }
#pragma unroll
            for (int i = 0; i < 4; i++)
#pragma unroll
                for (int j = 0; j < 4; j++)
                    mma16816(acc[i][j], Ah[i], Bh[j]);
        }
        __syncthreads();
    }
#undef ISSUE

    const int er = lane >> 2;
    const int ec = (lane & 3) * 2;
    if (mode == 0) {
        const int p = j0 >> 9;
        __half* dst = (p == 0 ? g_qh : (p == 1 ? g_kh : g_vh));
#pragma unroll
        for (int i = 0; i < 4; i++) {
#pragma unroll
            for (int j = 0; j < 4; j++) {
                int col = j0 + wn * 32 + j * 8 + ec;
                int hh = (col >> 6) & 7, d0 = col & 63;
#pragma unroll
                for (int half = 0; half < 2; half++) {
                    int m = m0 + wm * 64 + i * 16 + er + half * 8;
                    int bb = m >> 13, n = m & 8191;
                    float v0 = acc[i][j][half * 2 + 0];
                    float v1 = acc[i][j][half * 2 + 1];
                    if (p < 2) {
                        v0 = (v0 > 0.f) ? (v0 + 1.f) : expf(v0);
                        v1 = (v1 > 0.f) ? (v1 + 1.f) : expf(v1);
                    }
                    size_t off = ((size_t)((bb << 3) + hh) * 8192 + n) * 64 + d0;
                    *(uint32_t*)(dst + off) = pack2h(v0, v1);
                }
            }
        }
    } else {
#pragma unroll
        for (int i = 0; i < 4; i++) {
#pragma unroll
            for (int j = 0; j < 4; j++) {
                int col = j0 + wn * 32 + j * 8 + ec;
                float b0 = bias[col], b1 = bias[col + 1];
#pragma unroll
                for (int half = 0; half < 2; half++) {
                    int m = m0 + wm * 64 + i * 16 + er + half * 8;
                    *(float2*)(out + (size_t)m * 512 + col) =
                        make_float2(acc[i][j][half * 2 + 0] + b0,
                                    acc[i][j][half * 2 + 1] + b1);
                }
            }
        }
    }
}
#undef STG

// ---------------------------------------------------------------------------
// Per-chunk S^T = V^T K via mma.sync (A = V trans, B = K trans, fp16)
// ---------------------------------------------------------------------------
__global__ __launch_bounds__(128) void k_chunk_kv() {
    __shared__ __align__(1024) char sm[16384];   // Kh@0, Vh@8192
    const uint32_t sb = smem_u32(sm);
    const int tid = threadIdx.x, lane = tid & 31, w = tid >> 5;
    const int bh = blockIdx.y, c = blockIdx.x;
    const size_t base = ((size_t)bh * 8192 + c * 64) * 64;

    const __half* srcs[2] = { g_kh + base, g_vh + base };
#pragma unroll
    for (int tI = 0; tI < 2; tI++) {
#pragma unroll
        for (int it = 0; it < 4; it++) {
            int f = tid + it * 128;
            int row = f >> 3, seg = f & 7;
            cp_async16(sb + tI * 8192 + (uint32_t)SWZ(row * 128 + seg * 16),
                       srcs[tI] + (size_t)row * 64 + seg * 8);
        }
    }
    CP_COMMIT(); CP_WAIT(0);
    __syncthreads();

    const int sArow = (lane & 7) + ((lane >> 4) & 1) * 8;
    const int sAcb  = ((lane >> 3) & 1) * 16;
    const int sBrow = (lane & 7) + ((lane >> 3) & 1) * 8;
    const int sBcb  = (lane >> 4) * 16;

    float acc[8][4];
#pragma unroll
    for (int j = 0; j < 8; j++)
#pragma unroll
        for (int q = 0; q < 4; q++) acc[j][q] = 0.f;

#pragma unroll
    for (int ks = 0; ks < 4; ks++) {
        uint32_t Ah[4];
        uint32_t aoff = (uint32_t)((ks * 16 + sArow) * 128 + w * 32 + sAcb);
        ldsm_x4_t(Ah, sb + 8192 + SWZ(aoff));    // Vh
#pragma unroll
        for (int dg = 0; dg < 4; dg++) {
            uint32_t Bh[4];
            uint32_t boff = (uint32_t)((ks * 16 + sBrow) * 128 + dg * 32 + sBcb);
            ldsm_x4_t(Bh, sb + SWZ(boff));       // Kh
            mma16816(acc[2 * dg],     Ah, Bh + 0);
            mma16816(acc[2 * dg + 1], Ah, Bh + 2);
        }
    }

    __half* Sh = g_sth + ((size_t)bh * NCq + c) * 4096;
#pragma unroll
    for (int j = 0; j < 8; j++) {
        int d = j * 8 + (lane & 3) * 2;
#pragma unroll
        for (int half = 0; half < 2; half++) {
            int e = w * 16 + (lane >> 2) + half * 8;
            *(uint32_t*)(Sh + (size_t)e * 64 + d) =
                pack2h(acc[j][half * 2], acc[j][half * 2 + 1]);
        }
    }
}

// ---------------------------------------------------------------------------
// Exclusive prefix over chunks (fp32 accumulation, half2-vectorized)
// ---------------------------------------------------------------------------
__global__ __launch_bounds__(256) void k_prefix() {
    const int bh = blockIdx.x >> 3;
    const int entry = ((blockIdx.x & 7) << 8) + threadIdx.x;   // 0..2047 (uint32 units)
    float run0 = 0.f, run1 = 0.f;
    size_t idx = (size_t)bh * NCq * 2048 + entry;
    const uint32_t* Sp = (const uint32_t*)g_sth;
    uint32_t* Pp = (uint32_t*)g_pth;
#pragma unroll 4
    for (int c = 0; c < NCq; c++) {
        __half2 s = *(const __half2*)&Sp[idx];
        Pp[idx] = pack2h(run0, run1);
        run0 += __low2float(s);
        run1 += __high2float(s);
        idx += 2048;
    }
}

// ---------------------------------------------------------------------------
// Tensor-core per-chunk attention: out = Q@P + tril(Q K^T)@V
// smem: Qh@0 Kh@8192 Vh@16384 Ph@24576  (4 x 8KB)
// ---------------------------------------------------------------------------
__global__ __launch_bounds__(128) void k_attn_mma() {
    extern __shared__ char smraw[];
    char* sm = (char*)(((uintptr_t)smraw + 1023) & ~(uintptr_t)1023);
    const uint32_t sb = smem_u32(sm);
    const int tid = threadIdx.x, lane = tid & 31, w = tid >> 5;
    const int bh = blockIdx.y, c = blockIdx.x;
    const int rw = (w + c) & 3;
    const size_t tbase = ((size_t)bh * 8192 + c * 64) * 64;
    const size_t pbase = (size_t)(bh * NCq + c) * 4096;

    const __half* srcs[4] = { g_qh + tbase, g_kh + tbase, g_vh + tbase, g_pth + pbase };
#pragma unroll
    for (int tI = 0; tI < 4; tI++) {
        const __half* s = srcs[tI];
#pragma unroll
        for (int it = 0; it < 4; it++) {
            int f = tid + it * 128;
            int row = f >> 3, seg = f & 7;
            cp_async16(sb + tI * 8192 + (uint32_t)SWZ(row * 128 + seg * 16),
                       s + (size_t)row * 64 + seg * 8);
        }
    }
    CP_COMMIT(); CP_WAIT(0);
    __syncthreads();

    const int aRow = rw * 16 + (lane & 15);
    const int aCb  = (lane >> 4) * 16;
    const int bRow = (lane & 7) + ((lane >> 4) & 1) * 8;
    const int bCb  = ((lane >> 3) & 1) * 16;
    const int tRow = (lane & 7) + ((lane >> 3) & 1) * 8;
    const int tCb  = (lane >> 4) * 16;

#define AADDR(ks)           (sb + (uint32_t)SWZ(aRow * 128 + (ks) * 32 + aCb))
#define BADDR(ofs, n0, ks)  (sb + (ofs) + (uint32_t)SWZ(((n0) + bRow) * 128 + (ks) * 32 + bCb))
#define BTADDR(ofs, ks, e0) (sb + (ofs) + (uint32_t)SWZ(((ks) * 16 + tRow) * 128 + (e0) * 2 + tCb))

    float acc[8][4];
    float wac[8][4];
#pragma unroll
    for (int j = 0; j < 8; j++)
#pragma unroll
        for (int q = 0; q < 4; q++) { acc[j][q] = 0.f; wac[j][q] = 0.f; }

#pragma unroll
    for (int ks = 0; ks < 4; ks++) {
        uint32_t Ah[4];
        ldsm_x4(Ah, AADDR(ks));           // Qh
#pragma unroll
        for (int jj = 0; jj < 4; jj++) {
            uint32_t Bh[4];
            ldsm_x4(Bh, BADDR(24576, jj * 16, ks));   // Ph
            mma16816(acc[2 * jj],     Ah, Bh + 0);
            mma16816(acc[2 * jj + 1], Ah, Bh + 2);
        }
#pragma unroll
        for (int jj = 0; jj < 4; jj++) {
            if (jj > rw) break;
            uint32_t Bh[4];
            ldsm_x4(Bh, BADDR(8192, jj * 16, ks));    // Kh
            mma16816(wac[2 * jj],     Ah, Bh + 0);
            mma16816(wac[2 * jj + 1], Ah, Bh + 2);
        }
    }

    const int tr0 = rw * 16 + (lane >> 2);
#pragma unroll
    for (int j = 0; j < 8; j++) {
        int s0 = j * 8 + (lane & 3) * 2;
        if (s0     > tr0)     wac[j][0] = 0.f;
        if (s0 + 1 > tr0)     wac[j][1] = 0.f;
        if (s0     > tr0 + 8) wac[j][2] = 0.f;
        if (s0 + 1 > tr0 + 8) wac[j][3] = 0.f;
    }

#pragma unroll
    for (int ks = 0; ks < 4; ks++) {
        if (ks > rw) break;
        uint32_t Wh[4];
        Wh[0] = pack2h(wac[2 * ks][0],     wac[2 * ks][1]);
        Wh[1] = pack2h(wac[2 * ks][2],     wac[2 * ks][3]);
        Wh[2] = pack2h(wac[2 * ks + 1][0], wac[2 * ks + 1][1]);
        Wh[3] = pack2h(wac[2 * ks + 1][2], wac[2 * ks + 1][3]);
#pragma unroll
        for (int jj = 0; jj < 4; jj++) {
            uint32_t Bh[4];
            ldsm_x4_t(Bh, BTADDR(16384, ks, jj * 16));   // Vh (trans)
            mma16816(acc[2 * jj],     Wh, Bh + 0);
            mma16816(acc[2 * jj + 1], Wh, Bh + 2);
        }
    }

    const int bb = bh >> 3, hh = bh & 7;
#pragma unroll
    for (int j = 0; j < 8; j++) {
        int e = j * 8 + (lane & 3) * 2;
#pragma unroll
        for (int half = 0; half < 2; half++) {
            int t = rw * 16 + (lane >> 2) + half * 8;
            int n = c * 64 + t;
            size_t off = ((size_t)bb * 8192 + n) * 512 + hh * 64 + e;
            *(uint32_t*)(g_oh + off) = pack2h(acc[j][half * 2], acc[j][half * 2 + 1]);
        }
    }
#undef AADDR
#undef BADDR
#undef BTADDR
}

// ---------------------------------------------------------------------------
extern "C" void kernel_launch(void* const* d_in, const int* in_sizes, int n_in,
                              void* d_out, int out_size) {
    const float* x     = (const float*)d_in[0];
    const float* Wqkv  = (const float*)d_in[1];
    const float* Wproj = (const float*)d_in[2];
    const float* bproj = (const float*)d_in[3];
    float* out = (float*)d_out;
    (void)in_sizes; (void)n_in; (void)out_size;

    const int gemm_smem = 2 * 32768 + 1024;   // 2-stage, 2 CTAs/SM
    cudaFuncSetAttribute(k_gemm_mma, cudaFuncAttributeMaxDynamicSharedMemorySize, gemm_smem);
    const int attn_smem = 4 * 8192 + 1024;
    cudaFuncSetAttribute(k_attn_mma, cudaFuncAttributeMaxDynamicSharedMemorySize, attn_smem);

    k_cvt_all<<<9216, 256>>>((const float4*)x, (const float4*)Wqkv, (const float4*)Wproj);

    dim3 g1(12, 128);
    k_gemm_mma<<<g1, 256, gemm_smem>>>(0, nullptr, nullptr);

    dim3 ga(NCq, BHq);
    k_chunk_kv<<<ga, 128>>>();
    k_prefix<<<128, 256>>>();
    k_attn_mma<<<ga, 128, attn_smem>>>();

    dim3 g2(4, 128);
    k_gemm_mma<<<g2, 256, gemm_smem>>>(1, bproj, out);
}